// round 10
// baseline (speedup 1.0000x reference)
#include <cuda_runtime.h>
#include <math.h>
#include <stdint.h>

#define NB 2
#define NC 64
#define HW 2304
#define INNER 64
#define HEADS 8
#define DH 8
#define MM 36
#define SCALE 0.35355339059327373f

// ---------------- scratch (device globals; no allocation allowed) ----------------
__device__ float g_qt[NB * HW * INNER];          // q channel-last: [b][p][c]
__device__ float g_kt[NB * HW * INNER];          // k channel-last: [b][p][c]
__device__ float4 g_vlo4[NB * HEADS * HW + 96];  // v channels 0..3 (+prefetch pad)
__device__ float4 g_vhi4[NB * HEADS * HW + 96];  // v channels 4..7 (+prefetch pad)
__device__ float g_qd[NB * INNER * MM];          // conv+gelu(q): [b][oc][pos36]
__device__ float g_kd[NB * INNER * MM];
__device__ float g_dots[NB * HEADS * MM * MM];   // [b][head][i36][j36]

// ---------------- kernel A: 1x1 conv qkv + layout transforms ----------------
__global__ void qkv_kernel(const float* __restrict__ f, const float* __restrict__ wqkv) {
    __shared__ float sF[64 * 32];   // [c][pp]
    int b = blockIdx.x / 72;
    int p0 = (blockIdx.x % 72) * 32;

    for (int idx = threadIdx.x; idx < 64 * 32; idx += 256) {
        int c = idx >> 5, pp = idx & 31;
        sF[idx] = f[(b * 64 + c) * HW + p0 + pp];
    }
    __syncthreads();

    int pp = threadIdx.x & 31;
    int o0 = threadIdx.x >> 5;   // 0..7
    int p = p0 + pp;
    for (int o = o0; o < 192; o += 8) {
        const float* wr = wqkv + o * 64;
        float a0 = 0.f, a1 = 0.f, a2 = 0.f, a3 = 0.f;
        #pragma unroll
        for (int c = 0; c < 16; c++) {
            a0 = fmaf(__ldg(&wr[c]),      sF[c * 32 + pp],        a0);
            a1 = fmaf(__ldg(&wr[c + 16]), sF[(c + 16) * 32 + pp], a1);
            a2 = fmaf(__ldg(&wr[c + 32]), sF[(c + 32) * 32 + pp], a2);
            a3 = fmaf(__ldg(&wr[c + 48]), sF[(c + 48) * 32 + pp], a3);
        }
        float acc = (a0 + a1) + (a2 + a3);
        if (o < 64) {
            g_qt[(b * HW + p) * 64 + o] = acc;
        } else if (o < 128) {
            g_kt[(b * HW + p) * 64 + (o - 64)] = acc;
        } else {
            int oi = o - 128;
            int hd = oi >> 3, c = oi & 7;
            float* vout = (float*)(c < 4 ? g_vlo4 : g_vhi4);
            vout[((size_t)(b * HEADS + hd) * HW + p) * 4 + (c & 3)] = acc;
        }
    }
}

// ---------------- kernel B: 11x11 stride-8 pad-2 conv + exact GELU ----------------
__global__ void conv_kernel(const float* __restrict__ wq, const float* __restrict__ bq,
                            const float* __restrict__ wk, const float* __restrict__ bk) {
    int bid = blockIdx.x;
    int half = bid & 1;
    int oc = (bid >> 1) & 63;
    int b  = (bid >> 7) & 1;
    int t  = bid >> 8;

    const float* wsrc = (t ? wk : wq) + oc * 64 * 121;   // layout [ic][tap], linear
    const float* in   = (t ? g_kt : g_qt) + b * HW * 64;

    __shared__ __align__(16) float sw[121 * 66];
    for (int idx = threadIdx.x; idx < 121 * 64; idx += 288) {
        int ic = idx / 121, tap = idx % 121;
        sw[tap * 66 + ic] = wsrc[idx];
    }
    __syncthreads();

    int warp = threadIdx.x >> 5, lane = threadIdx.x & 31;
    int pos0 = half * 18 + warp * 2;

    int oh0 = pos0 / 6, ow0 = pos0 % 6;
    int oh1 = (pos0 + 1) / 6, ow1 = (pos0 + 1) % 6;
    int ihb0 = oh0 * 8 - 2, iwb0 = ow0 * 8 - 2;
    int ihb1 = oh1 * 8 - 2, iwb1 = ow1 * 8 - 2;

    float2 a0 = {0.f, 0.f}, a1 = {0.f, 0.f};
    #pragma unroll
    for (int kh = 0; kh < 11; kh++) {
        #pragma unroll
        for (int kw = 0; kw < 11; kw++) {
            const float2* wp2 = (const float2*)(sw + (kh * 11 + kw) * 66);
            float2 wv = wp2[lane];
            int ih0 = ihb0 + kh, iw0 = iwb0 + kw;
            if ((unsigned)ih0 < 48u && (unsigned)iw0 < 48u) {
                const float2* ip = (const float2*)(in + (ih0 * 48 + iw0) * 64);
                float2 iv = ip[lane];
                a0.x = fmaf(iv.x, wv.x, a0.x);
                a0.y = fmaf(iv.y, wv.y, a0.y);
            }
            int ih1 = ihb1 + kh, iw1 = iwb1 + kw;
            if ((unsigned)ih1 < 48u && (unsigned)iw1 < 48u) {
                const float2* ip = (const float2*)(in + (ih1 * 48 + iw1) * 64);
                float2 iv = ip[lane];
                a1.x = fmaf(iv.x, wv.x, a1.x);
                a1.y = fmaf(iv.y, wv.y, a1.y);
            }
        }
    }
    float acc0 = a0.x + a0.y;
    float acc1 = a1.x + a1.y;
    #pragma unroll
    for (int off = 16; off; off >>= 1) {
        acc0 += __shfl_xor_sync(0xffffffffu, acc0, off);
        acc1 += __shfl_xor_sync(0xffffffffu, acc1, off);
    }
    if (lane == 0) {
        float bias = (t ? bk : bq)[oc];
        float* dst = (t ? g_kd : g_qd) + (b * 64 + oc) * MM;
        float x0 = acc0 + bias;
        dst[pos0] = 0.5f * x0 * (1.0f + erff(x0 * 0.7071067811865476f));
        float x1 = acc1 + bias;
        dst[pos0 + 1] = 0.5f * x1 * (1.0f + erff(x1 * 0.7071067811865476f));
    }
}

// ---------------- kernel C: dots[b,h,i36,j36] ----------------
__global__ void dots_kernel() {
    int idx = blockIdx.x * 256 + threadIdx.x;
    if (idx >= NB * HEADS * MM * MM) return;
    int j  = idx % 36;
    int i  = (idx / 36) % 36;
    int bh = idx / (36 * 36);
    int b = bh >> 3, hd = bh & 7;
    const float* qd = g_qd + (b * 64 + hd * 8) * MM;
    const float* kd = g_kd + (b * 64 + hd * 8) * MM;
    float s = 0.f;
    #pragma unroll
    for (int c = 0; c < 8; c++) s = fmaf(qd[c * MM + i], kd[c * MM + j], s);
    g_dots[idx] = s * SCALE;
}

// ---------------- kernel D: fused pos-logits + softmax + attn@v ----------------
// one warp per 8 consecutive output rows; phase-major main loop + rolling prefetch
// grid: 36864/8/4 = 1152 blocks, 128 threads (4 warps)

#define FMA2(d, a, b, c) asm("fma.rn.f32x2 %0, %1, %2, %3;" : "=l"(d) : "l"(a), "l"(b), "l"(c))
#define PACK2(out, x)    asm("mov.b64 %0, {%1, %1};" : "=l"(out) : "r"(x))
#define UNPK2(lo, hi, in) asm("mov.b64 {%0, %1}, %2;" : "=r"(lo), "=r"(hi) : "l"(in))

// per-warp smem floats:
//  0    sQ[64]      (dead after sA/sB built; smB[24] aliased here)
//  64   sD[40]
//  104  sA[8*48]
//  488  sB[8*48]
//  872  eC2[150*8]  ([s][r]; 872*4 % 16 == 0; 150 covers s+6 prefetch to 149)
//  2072 rsum[8]
#define WSH 2080

__global__ void __launch_bounds__(128, 4)
attn_kernel(const float* __restrict__ pos_h, const float* __restrict__ pos_w,
            float* __restrict__ out) {
    __shared__ float sh[4][WSH];
    int warp = threadIdx.x >> 5, lane = threadIdx.x & 31;
    int w = blockIdx.x * 4 + warp;              // global warp id < 4608
    int bh = w / 288;                           // 2304/8 = 288 row-groups per (b,h)
    int i0 = (w % 288) * 8;
    int b = bh >> 3, hd = bh & 7;

    float* sQ   = sh[warp];          // 64
    float* sD   = sh[warp] + 64;     // 40
    float* sA   = sh[warp] + 104;    // 8*48
    float* sB   = sh[warp] + 488;    // 8*48
    float* eC2  = sh[warp] + 872;    // 150*8, [s][r]
    float* rsum = sh[warp] + 2072;   // 8
    float* smB  = sh[warp];          // alias sQ: sumB16[r*3+phi], 24

    // stage q for 8 rows: sQ[r*8+c]
    {
        int t = lane;
        sQ[t] = g_qt[((size_t)(b * HW + i0 + (t >> 3))) * 64 + hd * 8 + (t & 7)];
        t += 32;
        sQ[t] = g_qt[((size_t)(b * HW + i0 + (t >> 3))) * 64 + hd * 8 + (t & 7)];
    }
    // raw D row (i0..i0+7 share i0>>6 since i0 % 8 == 0)
    {
        const float* dsrc = g_dots + ((b * HEADS + hd) * MM + (i0 >> 6)) * MM;
        for (int t = lane; t < 36; t += 32) sD[t] = dsrc[t];
    }
    __syncwarp();

    // raw A/B for 8 rows
    for (int jh = lane; jh < 48; jh += 32) {
        float phv[8], pwv[8];
        #pragma unroll
        for (int c = 0; c < 8; c++) {
            phv[c] = __ldg(&pos_h[c * 48 + jh]);
            pwv[c] = __ldg(&pos_w[c * 48 + jh]);
        }
        #pragma unroll
        for (int r = 0; r < 8; r++) {
            float a = 0.f, bb = 0.f;
            #pragma unroll
            for (int c = 0; c < 8; c++) {
                float qv = sQ[r * 8 + c];
                a  = fmaf(qv, phv[c], a);
                bb = fmaf(qv, pwv[c], bb);
            }
            sA[r * 48 + jh] = a;
            sB[r * 48 + jh] = bb;
        }
    }
    __syncwarp();

    // per-component maxes
    float mA[8], mB[8], mD = -1e30f;
    #pragma unroll
    for (int r = 0; r < 8; r++) { mA[r] = -1e30f; mB[r] = -1e30f; }
    for (int t = lane; t < 48; t += 32) {
        #pragma unroll
        for (int r = 0; r < 8; r++) {
            mA[r] = fmaxf(mA[r], sA[r * 48 + t]);
            mB[r] = fmaxf(mB[r], sB[r * 48 + t]);
        }
    }
    for (int t = lane; t < 36; t += 32) mD = fmaxf(mD, sD[t]);
    #pragma unroll
    for (int off = 16; off; off >>= 1) {
        mD = fmaxf(mD, __shfl_xor_sync(0xffffffffu, mD, off));
        #pragma unroll
        for (int r = 0; r < 8; r++) {
            mA[r] = fmaxf(mA[r], __shfl_xor_sync(0xffffffffu, mA[r], off));
            mB[r] = fmaxf(mB[r], __shfl_xor_sync(0xffffffffu, mB[r], off));
        }
    }
    __syncwarp();

    // exponentiate in place
    for (int t = lane; t < 36; t += 32) sD[t] = __expf(sD[t] - mD);
    for (int t = lane; t < 48; t += 32) {
        #pragma unroll
        for (int r = 0; r < 8; r++) {
            sA[r * 48 + t] = __expf(sA[r * 48 + t] - mA[r]);
            sB[r * 48 + t] = __expf(sB[r * 48 + t] - mB[r]);
        }
    }
    __syncwarp();

    // eC2[s][r] = eA[r][s/3] * eD[s>>2]
    for (int s = lane; s < 144; s += 32) {
        float d = sD[s >> 2];
        int jh = s / 3;
        float4 v0, v1;
        v0.x = sA[0 * 48 + jh] * d;  v0.y = sA[1 * 48 + jh] * d;
        v0.z = sA[2 * 48 + jh] * d;  v0.w = sA[3 * 48 + jh] * d;
        v1.x = sA[4 * 48 + jh] * d;  v1.y = sA[5 * 48 + jh] * d;
        v1.z = sA[6 * 48 + jh] * d;  v1.w = sA[7 * 48 + jh] * d;
        *(float4*)&eC2[s * 8]     = v0;
        *(float4*)&eC2[s * 8 + 4] = v1;
    }
    // zero prefetch pad rows s=144..149 (read but must not be NaN garbage? values
    // are multiplied into discarded q's only at k=23 prefetch; still keep defined)
    for (int s = 144 + lane; s < 150; s += 32) {
        *(float4*)&eC2[s * 8]     = make_float4(0.f, 0.f, 0.f, 0.f);
        *(float4*)&eC2[s * 8 + 4] = make_float4(0.f, 0.f, 0.f, 0.f);
    }
    __syncwarp();

    // sumB16[r][phi] into smB (sQ dead)
    if (lane < 24) {
        int r = lane / 3, phi = lane % 3;
        float s16 = 0.f;
        #pragma unroll
        for (int u = 0; u < 16; u++) s16 += sB[r * 48 + phi * 16 + u];
        smB[r * 3 + phi] = s16;
    }
    __syncwarp();

    // row sums: ssum[r] = sum_s eC2[s][r] * sumB16[r][s%3]; reduce and park in rsum
    {
        float ssum[8] = {0.f, 0.f, 0.f, 0.f, 0.f, 0.f, 0.f, 0.f};
        for (int s = lane; s < 144; s += 32) {
            int phi = s % 3;
            float4 c0 = *(const float4*)&eC2[s * 8];
            float4 c1 = *(const float4*)&eC2[s * 8 + 4];
            ssum[0] = fmaf(c0.x, smB[0 + phi],  ssum[0]);
            ssum[1] = fmaf(c0.y, smB[3 + phi],  ssum[1]);
            ssum[2] = fmaf(c0.z, smB[6 + phi],  ssum[2]);
            ssum[3] = fmaf(c0.w, smB[9 + phi],  ssum[3]);
            ssum[4] = fmaf(c1.x, smB[12 + phi], ssum[4]);
            ssum[5] = fmaf(c1.y, smB[15 + phi], ssum[5]);
            ssum[6] = fmaf(c1.z, smB[18 + phi], ssum[6]);
            ssum[7] = fmaf(c1.w, smB[21 + phi], ssum[7]);
        }
        #pragma unroll
        for (int off = 16; off; off >>= 1) {
            #pragma unroll
            for (int r = 0; r < 8; r++)
                ssum[r] += __shfl_xor_sync(0xffffffffu, ssum[r], off);
        }
        if (lane == 0) {
            #pragma unroll
            for (int r = 0; r < 8; r++) rsum[r] = ssum[r];
        }
    }
    __syncwarp();

    const ulonglong2* vlo = (const ulonglong2*)g_vlo4 + (size_t)(b * HEADS + hd) * HW;
    const ulonglong2* vhi = (const ulonglong2*)g_vhi4 + (size_t)(b * HEADS + hd) * HW;

    unsigned long long acc[8][4];
    #pragma unroll
    for (int r = 0; r < 8; r++)
        #pragma unroll
        for (int k = 0; k < 4; k++) acc[r][k] = 0ull;

    // phase-major main loop: phase p, j = lane + 32p + 96k (k=0..23)
    // jw = (lane+32p) % 48 constant per phase; s = ((lane+32p)>>4) + 6k
    #pragma unroll 1
    for (int phase = 0; phase < 3; phase++) {
        int jp = lane + 32 * phase;          // < 96
        int jw = (jp >= 48) ? jp - 48 : jp;
        float bv[8];
        #pragma unroll
        for (int r = 0; r < 8; r++) bv[r] = sB[r * 48 + jw];

        int j = jp;
        int s = jp >> 4;
        ulonglong2 L = vlo[j], H = vhi[j];
        float4 c0 = *(const float4*)&eC2[s * 8];
        float4 c1 = *(const float4*)&eC2[s * 8 + 4];

        #pragma unroll 1
        for (int k = 0; k < 24; k++) {
            // rolling prefetch for next step (pad guarantees in-bounds at k=23)
            ulonglong2 Ln = vlo[j + 96];
            ulonglong2 Hn = vhi[j + 96];
            float4 c0n = *(const float4*)&eC2[(s + 6) * 8];
            float4 c1n = *(const float4*)&eC2[(s + 6) * 8 + 4];

            unsigned long long q;
            PACK2(q, __float_as_uint(c0.x * bv[0]));
            FMA2(acc[0][0], q, L.x, acc[0][0]); FMA2(acc[0][1], q, L.y, acc[0][1]);
            FMA2(acc[0][2], q, H.x, acc[0][2]); FMA2(acc[0][3], q, H.y, acc[0][3]);
            PACK2(q, __float_as_uint(c0.y * bv[1]));
            FMA2(acc[1][0], q, L.x, acc[1][0]); FMA2(acc[1][1], q, L.y, acc[1][1]);
            FMA2(acc[1][2], q, H.x, acc[1][2]); FMA2(acc[1][3], q, H.y, acc[1][3]);
            PACK2(q, __float_as_uint(c0.z * bv[2]));
            FMA2(acc[2][0], q, L.x, acc[2][0]); FMA2(acc[2][1], q, L.y, acc[2][1]);
            FMA2(acc[2][2], q, H.x, acc[2][2]); FMA2(acc[2][3], q, H.y, acc[2][3]);
            PACK2(q, __float_as_uint(c0.w * bv[3]));
            FMA2(acc[3][0], q, L.x, acc[3][0]); FMA2(acc[3][1], q, L.y, acc[3][1]);
            FMA2(acc[3][2], q, H.x, acc[3][2]); FMA2(acc[3][3], q, H.y, acc[3][3]);
            PACK2(q, __float_as_uint(c1.x * bv[4]));
            FMA2(acc[4][0], q, L.x, acc[4][0]); FMA2(acc[4][1], q, L.y, acc[4][1]);
            FMA2(acc[4][2], q, H.x, acc[4][2]); FMA2(acc[4][3], q, H.y, acc[4][3]);
            PACK2(q, __float_as_uint(c1.y * bv[5]));
            FMA2(acc[5][0], q, L.x, acc[5][0]); FMA2(acc[5][1], q, L.y, acc[5][1]);
            FMA2(acc[5][2], q, H.x, acc[5][2]); FMA2(acc[5][3], q, H.y, acc[5][3]);
            PACK2(q, __float_as_uint(c1.z * bv[6]));
            FMA2(acc[6][0], q, L.x, acc[6][0]); FMA2(acc[6][1], q, L.y, acc[6][1]);
            FMA2(acc[6][2], q, H.x, acc[6][2]); FMA2(acc[6][3], q, H.y, acc[6][3]);
            PACK2(q, __float_as_uint(c1.w * bv[7]));
            FMA2(acc[7][0], q, L.x, acc[7][0]); FMA2(acc[7][1], q, L.y, acc[7][1]);
            FMA2(acc[7][2], q, H.x, acc[7][2]); FMA2(acc[7][3], q, H.y, acc[7][3]);

            L = Ln; H = Hn; c0 = c0n; c1 = c1n;
            j += 96; s += 6;
        }
    }

    // reduce + write 8 rows
    #pragma unroll
    for (int r = 0; r < 8; r++) {
        float f0, f1, f2, f3, f4, f5, f6, f7;
        unsigned u0, u1;
        UNPK2(u0, u1, acc[r][0]); f0 = __uint_as_float(u0); f1 = __uint_as_float(u1);
        UNPK2(u0, u1, acc[r][1]); f2 = __uint_as_float(u0); f3 = __uint_as_float(u1);
        UNPK2(u0, u1, acc[r][2]); f4 = __uint_as_float(u0); f5 = __uint_as_float(u1);
        UNPK2(u0, u1, acc[r][3]); f6 = __uint_as_float(u0); f7 = __uint_as_float(u1);
        #pragma unroll
        for (int off = 16; off; off >>= 1) {
            f0 += __shfl_xor_sync(0xffffffffu, f0, off);
            f1 += __shfl_xor_sync(0xffffffffu, f1, off);
            f2 += __shfl_xor_sync(0xffffffffu, f2, off);
            f3 += __shfl_xor_sync(0xffffffffu, f3, off);
            f4 += __shfl_xor_sync(0xffffffffu, f4, off);
            f5 += __shfl_xor_sync(0xffffffffu, f5, off);
            f6 += __shfl_xor_sync(0xffffffffu, f6, off);
            f7 += __shfl_xor_sync(0xffffffffu, f7, off);
        }
        float rr = f0;
        if (lane == 1) rr = f1;
        if (lane == 2) rr = f2;
        if (lane == 3) rr = f3;
        if (lane == 4) rr = f4;
        if (lane == 5) rr = f5;
        if (lane == 6) rr = f6;
        if (lane == 7) rr = f7;
        if (lane < 8)
            out[((size_t)(b * 64) + hd * 8 + lane) * HW + i0 + r] = rr / rsum[r];
    }
}

// ---------------- launch ----------------
extern "C" void kernel_launch(void* const* d_in, const int* in_sizes, int n_in,
                              void* d_out, int out_size) {
    const float* f    = (const float*)d_in[0];
    const float* wqkv = (const float*)d_in[1];
    const float* wq   = (const float*)d_in[2];
    const float* bq   = (const float*)d_in[3];
    const float* wk   = (const float*)d_in[4];
    const float* bk   = (const float*)d_in[5];
    const float* ph   = (const float*)d_in[6];
    const float* pw   = (const float*)d_in[7];
    float* out = (float*)d_out;

    qkv_kernel<<<144, 256>>>(f, wqkv);
    conv_kernel<<<512, 288>>>(wq, bq, wk, bk);
    dots_kernel<<<81, 256>>>();
    attn_kernel<<<1152, 128>>>(ph, pw, out);
}

// round 11
// speedup vs baseline: 1.2466x; 1.2466x over previous
#include <cuda_runtime.h>
#include <math.h>
#include <stdint.h>

#define NB 2
#define NC 64
#define HW 2304
#define INNER 64
#define HEADS 8
#define DH 8
#define MM 36
#define SCALE 0.35355339059327373f

// ---------------- scratch (device globals; no allocation allowed) ----------------
__device__ float g_qt[NB * HW * INNER];          // q channel-last: [b][p][c]
__device__ float g_kt[NB * HW * INNER];          // k channel-last: [b][p][c]
__device__ float4 g_vlo4[NB * HEADS * HW];       // v channels 0..3:  [b][head][j]
__device__ float4 g_vhi4[NB * HEADS * HW];       // v channels 4..7
__device__ float g_qd[NB * INNER * MM];          // conv+gelu(q): [b][oc][pos36]
__device__ float g_kd[NB * INNER * MM];

// ---------------- kernel A: 1x1 conv qkv + layout transforms ----------------
__global__ void qkv_kernel(const float* __restrict__ f, const float* __restrict__ wqkv) {
    __shared__ float sF[64 * 32];   // [c][pp]
    int b = blockIdx.x / 72;
    int p0 = (blockIdx.x % 72) * 32;

    for (int idx = threadIdx.x; idx < 64 * 32; idx += 256) {
        int c = idx >> 5, pp = idx & 31;
        sF[idx] = f[(b * 64 + c) * HW + p0 + pp];
    }
    __syncthreads();

    int pp = threadIdx.x & 31;
    int o0 = threadIdx.x >> 5;   // 0..7
    int p = p0 + pp;
    for (int o = o0; o < 192; o += 8) {
        const float* wr = wqkv + o * 64;
        float a0 = 0.f, a1 = 0.f, a2 = 0.f, a3 = 0.f;
        #pragma unroll
        for (int c = 0; c < 16; c++) {
            a0 = fmaf(__ldg(&wr[c]),      sF[c * 32 + pp],        a0);
            a1 = fmaf(__ldg(&wr[c + 16]), sF[(c + 16) * 32 + pp], a1);
            a2 = fmaf(__ldg(&wr[c + 32]), sF[(c + 32) * 32 + pp], a2);
            a3 = fmaf(__ldg(&wr[c + 48]), sF[(c + 48) * 32 + pp], a3);
        }
        float acc = (a0 + a1) + (a2 + a3);
        if (o < 64) {
            g_qt[(b * HW + p) * 64 + o] = acc;
        } else if (o < 128) {
            g_kt[(b * HW + p) * 64 + (o - 64)] = acc;
        } else {
            int oi = o - 128;
            int hd = oi >> 3, c = oi & 7;
            float* vout = (float*)(c < 4 ? g_vlo4 : g_vhi4);
            vout[((size_t)(b * HEADS + hd) * HW + p) * 4 + (c & 3)] = acc;
        }
    }
}

// ---------------- kernel B: 11x11 stride-8 pad-2 conv + exact GELU ----------------
__global__ void conv_kernel(const float* __restrict__ wq, const float* __restrict__ bq,
                            const float* __restrict__ wk, const float* __restrict__ bk) {
    int bid = blockIdx.x;
    int half = bid & 1;
    int oc = (bid >> 1) & 63;
    int b  = (bid >> 7) & 1;
    int t  = bid >> 8;

    const float* wsrc = (t ? wk : wq) + oc * 64 * 121;   // layout [ic][tap], linear
    const float* in   = (t ? g_kt : g_qt) + b * HW * 64;

    __shared__ __align__(16) float sw[121 * 66];
    for (int idx = threadIdx.x; idx < 121 * 64; idx += 288) {
        int ic = idx / 121, tap = idx % 121;
        sw[tap * 66 + ic] = wsrc[idx];
    }
    __syncthreads();

    int warp = threadIdx.x >> 5, lane = threadIdx.x & 31;
    int pos0 = half * 18 + warp * 2;

    int oh0 = pos0 / 6, ow0 = pos0 % 6;
    int oh1 = (pos0 + 1) / 6, ow1 = (pos0 + 1) % 6;
    int ihb0 = oh0 * 8 - 2, iwb0 = ow0 * 8 - 2;
    int ihb1 = oh1 * 8 - 2, iwb1 = ow1 * 8 - 2;

    float2 a0 = {0.f, 0.f}, a1 = {0.f, 0.f};
    #pragma unroll
    for (int kh = 0; kh < 11; kh++) {
        #pragma unroll
        for (int kw = 0; kw < 11; kw++) {
            const float2* wp2 = (const float2*)(sw + (kh * 11 + kw) * 66);
            float2 wv = wp2[lane];
            int ih0 = ihb0 + kh, iw0 = iwb0 + kw;
            if ((unsigned)ih0 < 48u && (unsigned)iw0 < 48u) {
                const float2* ip = (const float2*)(in + (ih0 * 48 + iw0) * 64);
                float2 iv = ip[lane];
                a0.x = fmaf(iv.x, wv.x, a0.x);
                a0.y = fmaf(iv.y, wv.y, a0.y);
            }
            int ih1 = ihb1 + kh, iw1 = iwb1 + kw;
            if ((unsigned)ih1 < 48u && (unsigned)iw1 < 48u) {
                const float2* ip = (const float2*)(in + (ih1 * 48 + iw1) * 64);
                float2 iv = ip[lane];
                a1.x = fmaf(iv.x, wv.x, a1.x);
                a1.y = fmaf(iv.y, wv.y, a1.y);
            }
        }
    }
    float acc0 = a0.x + a0.y;
    float acc1 = a1.x + a1.y;
    #pragma unroll
    for (int off = 16; off; off >>= 1) {
        acc0 += __shfl_xor_sync(0xffffffffu, acc0, off);
        acc1 += __shfl_xor_sync(0xffffffffu, acc1, off);
    }
    if (lane == 0) {
        float bias = (t ? bk : bq)[oc];
        float* dst = (t ? g_kd : g_qd) + (b * 64 + oc) * MM;
        float x0 = acc0 + bias;
        dst[pos0] = 0.5f * x0 * (1.0f + erff(x0 * 0.7071067811865476f));
        float x1 = acc1 + bias;
        dst[pos0 + 1] = 0.5f * x1 * (1.0f + erff(x1 * 0.7071067811865476f));
    }
}

// ---------------- kernel D: fused dots + pos-logits + softmax + attn@v ----------------
// one warp per 8 consecutive output rows (same b,head, same D-row since i0%8==0)
// grid: 36864/8/4 = 1152 blocks, 128 threads (4 warps)   [r9 design + inline D]

#define FMA2(d, a, b, c) asm("fma.rn.f32x2 %0, %1, %2, %3;" : "=l"(d) : "l"(a), "l"(b), "l"(c))
#define PACK2(out, x)    asm("mov.b64 %0, {%1, %1};" : "=l"(out) : "r"(x))
#define UNPK2(lo, hi, in) asm("mov.b64 {%0, %1}, %2;" : "=r"(lo), "=r"(hi) : "l"(in))

// per-warp smem floats:
//  0    sQ[64]      (dead after sA/sB built; smB[24] aliased here)
//  64   sD[40]
//  104  sA[8*48]
//  488  sB[8*48]
//  872  eC2[144*8]  (layout [s][r], 16B-aligned: 872*4 % 16 == 0)
//  2024 rsum[8]
#define WSH 2032

__global__ void __launch_bounds__(128, 4)
attn_kernel(const float* __restrict__ pos_h, const float* __restrict__ pos_w,
            float* __restrict__ out) {
    __shared__ float sh[4][WSH];
    int warp = threadIdx.x >> 5, lane = threadIdx.x & 31;
    int w = blockIdx.x * 4 + warp;              // global warp id < 4608
    int bh = w / 288;                           // 2304/8 = 288 row-groups per (b,h)
    int i0 = (w % 288) * 8;
    int b = bh >> 3, hd = bh & 7;

    float* sQ   = sh[warp];          // 64
    float* sD   = sh[warp] + 64;     // 40
    float* sA   = sh[warp] + 104;    // 8*48
    float* sB   = sh[warp] + 488;    // 8*48
    float* eC2  = sh[warp] + 872;    // 144*8, [s][r]
    float* rsum = sh[warp] + 2024;   // 8
    float* smB  = sh[warp];          // alias sQ: sumB16[r*3+phi], 24

    // stage q for 8 rows: sQ[r*8+c]
    {
        int t = lane;
        sQ[t] = g_qt[((size_t)(b * HW + i0 + (t >> 3))) * 64 + hd * 8 + (t & 7)];
        t += 32;
        sQ[t] = g_qt[((size_t)(b * HW + i0 + (t >> 3))) * 64 + hd * 8 + (t & 7)];
    }
    // inline dots: sD[t] = SCALE * sum_c qd[c][i36] * kd[c][t]   (i36 = i0>>6)
    {
        int i36 = i0 >> 6;
        const float* qd = g_qd + (b * 64 + hd * 8) * MM;
        const float* kd = g_kd + (b * 64 + hd * 8) * MM;
        for (int t = lane; t < 36; t += 32) {
            float s = 0.f;
            #pragma unroll
            for (int c = 0; c < 8; c++)
                s = fmaf(__ldg(&qd[c * MM + i36]), __ldg(&kd[c * MM + t]), s);
            sD[t] = s * SCALE;
        }
    }
    __syncwarp();

    // raw A/B for 8 rows
    for (int jh = lane; jh < 48; jh += 32) {
        float phv[8], pwv[8];
        #pragma unroll
        for (int c = 0; c < 8; c++) {
            phv[c] = __ldg(&pos_h[c * 48 + jh]);
            pwv[c] = __ldg(&pos_w[c * 48 + jh]);
        }
        #pragma unroll
        for (int r = 0; r < 8; r++) {
            float a = 0.f, bb = 0.f;
            #pragma unroll
            for (int c = 0; c < 8; c++) {
                float qv = sQ[r * 8 + c];
                a  = fmaf(qv, phv[c], a);
                bb = fmaf(qv, pwv[c], bb);
            }
            sA[r * 48 + jh] = a;
            sB[r * 48 + jh] = bb;
        }
    }
    __syncwarp();

    // per-component maxes
    float mA[8], mB[8], mD = -1e30f;
    #pragma unroll
    for (int r = 0; r < 8; r++) { mA[r] = -1e30f; mB[r] = -1e30f; }
    for (int t = lane; t < 48; t += 32) {
        #pragma unroll
        for (int r = 0; r < 8; r++) {
            mA[r] = fmaxf(mA[r], sA[r * 48 + t]);
            mB[r] = fmaxf(mB[r], sB[r * 48 + t]);
        }
    }
    for (int t = lane; t < 36; t += 32) mD = fmaxf(mD, sD[t]);
    #pragma unroll
    for (int off = 16; off; off >>= 1) {
        mD = fmaxf(mD, __shfl_xor_sync(0xffffffffu, mD, off));
        #pragma unroll
        for (int r = 0; r < 8; r++) {
            mA[r] = fmaxf(mA[r], __shfl_xor_sync(0xffffffffu, mA[r], off));
            mB[r] = fmaxf(mB[r], __shfl_xor_sync(0xffffffffu, mB[r], off));
        }
    }
    __syncwarp();

    // exponentiate in place
    for (int t = lane; t < 36; t += 32) sD[t] = __expf(sD[t] - mD);
    for (int t = lane; t < 48; t += 32) {
        #pragma unroll
        for (int r = 0; r < 8; r++) {
            sA[r * 48 + t] = __expf(sA[r * 48 + t] - mA[r]);
            sB[r * 48 + t] = __expf(sB[r * 48 + t] - mB[r]);
        }
    }
    __syncwarp();

    // eC2[s][r] = eA[r][s/3] * eD[s>>2]
    for (int s = lane; s < 144; s += 32) {
        float d = sD[s >> 2];
        int jh = s / 3;
        float4 v0, v1;
        v0.x = sA[0 * 48 + jh] * d;  v0.y = sA[1 * 48 + jh] * d;
        v0.z = sA[2 * 48 + jh] * d;  v0.w = sA[3 * 48 + jh] * d;
        v1.x = sA[4 * 48 + jh] * d;  v1.y = sA[5 * 48 + jh] * d;
        v1.z = sA[6 * 48 + jh] * d;  v1.w = sA[7 * 48 + jh] * d;
        *(float4*)&eC2[s * 8]     = v0;
        *(float4*)&eC2[s * 8 + 4] = v1;
    }
    __syncwarp();

    // register b-values: jw = (lane + 32t) % 48 has period 3 in t
    int w0 = lane;
    int w1 = (lane < 16) ? lane + 32 : lane - 16;
    int w2 = lane + 16;
    float bva[8], bvb[8], bvc[8];
    #pragma unroll
    for (int r = 0; r < 8; r++) {
        bva[r] = sB[r * 48 + w0];
        bvb[r] = sB[r * 48 + w1];
        bvc[r] = sB[r * 48 + w2];
    }

    // sumB16[r][phi] into smB (sQ dead)
    if (lane < 24) {
        int r = lane / 3, phi = lane % 3;
        float s16 = 0.f;
        #pragma unroll
        for (int u = 0; u < 16; u++) s16 += sB[r * 48 + phi * 16 + u];
        smB[r * 3 + phi] = s16;
    }
    __syncwarp();

    // row sums: ssum[r] = sum_s eC2[s][r] * sumB16[r][s%3]; reduce and park in rsum
    {
        float ssum[8] = {0.f, 0.f, 0.f, 0.f, 0.f, 0.f, 0.f, 0.f};
        for (int s = lane; s < 144; s += 32) {
            int phi = s % 3;
            float4 c0 = *(const float4*)&eC2[s * 8];
            float4 c1 = *(const float4*)&eC2[s * 8 + 4];
            ssum[0] = fmaf(c0.x, smB[0 + phi],  ssum[0]);
            ssum[1] = fmaf(c0.y, smB[3 + phi],  ssum[1]);
            ssum[2] = fmaf(c0.z, smB[6 + phi],  ssum[2]);
            ssum[3] = fmaf(c0.w, smB[9 + phi],  ssum[3]);
            ssum[4] = fmaf(c1.x, smB[12 + phi], ssum[4]);
            ssum[5] = fmaf(c1.y, smB[15 + phi], ssum[5]);
            ssum[6] = fmaf(c1.z, smB[18 + phi], ssum[6]);
            ssum[7] = fmaf(c1.w, smB[21 + phi], ssum[7]);
        }
        #pragma unroll
        for (int off = 16; off; off >>= 1) {
            #pragma unroll
            for (int r = 0; r < 8; r++)
                ssum[r] += __shfl_xor_sync(0xffffffffu, ssum[r], off);
        }
        if (lane == 0) {
            #pragma unroll
            for (int r = 0; r < 8; r++) rsum[r] = ssum[r];
        }
    }
    __syncwarp();

    const ulonglong2* vlo = (const ulonglong2*)g_vlo4 + (size_t)(b * HEADS + hd) * HW;
    const ulonglong2* vhi = (const ulonglong2*)g_vhi4 + (size_t)(b * HEADS + hd) * HW;

    unsigned long long acc[8][4];
    #pragma unroll
    for (int r = 0; r < 8; r++)
        #pragma unroll
        for (int k = 0; k < 4; k++) acc[r][k] = 0ull;

    // main loop: j = lane + 32t, t = 0..71; 3-phase unroll; s = (lane>>4) + 2t
    int j = lane;
    int s = lane >> 4;

#define STEP(JOFS, SOFS, BV) { \
        ulonglong2 L = vlo[j + (JOFS)]; \
        ulonglong2 H = vhi[j + (JOFS)]; \
        float4 c0 = *(const float4*)&eC2[(s + (SOFS)) * 8]; \
        float4 c1 = *(const float4*)&eC2[(s + (SOFS)) * 8 + 4]; \
        unsigned long long q0, q1, q2, q3, q4, q5, q6, q7; \
        PACK2(q0, __float_as_uint(c0.x * BV[0])); \
        PACK2(q1, __float_as_uint(c0.y * BV[1])); \
        PACK2(q2, __float_as_uint(c0.z * BV[2])); \
        PACK2(q3, __float_as_uint(c0.w * BV[3])); \
        PACK2(q4, __float_as_uint(c1.x * BV[4])); \
        PACK2(q5, __float_as_uint(c1.y * BV[5])); \
        PACK2(q6, __float_as_uint(c1.z * BV[6])); \
        PACK2(q7, __float_as_uint(c1.w * BV[7])); \
        FMA2(acc[0][0], q0, L.x, acc[0][0]); FMA2(acc[0][1], q0, L.y, acc[0][1]); \
        FMA2(acc[0][2], q0, H.x, acc[0][2]); FMA2(acc[0][3], q0, H.y, acc[0][3]); \
        FMA2(acc[1][0], q1, L.x, acc[1][0]); FMA2(acc[1][1], q1, L.y, acc[1][1]); \
        FMA2(acc[1][2], q1, H.x, acc[1][2]); FMA2(acc[1][3], q1, H.y, acc[1][3]); \
        FMA2(acc[2][0], q2, L.x, acc[2][0]); FMA2(acc[2][1], q2, L.y, acc[2][1]); \
        FMA2(acc[2][2], q2, H.x, acc[2][2]); FMA2(acc[2][3], q2, H.y, acc[2][3]); \
        FMA2(acc[3][0], q3, L.x, acc[3][0]); FMA2(acc[3][1], q3, L.y, acc[3][1]); \
        FMA2(acc[3][2], q3, H.x, acc[3][2]); FMA2(acc[3][3], q3, H.y, acc[3][3]); \
        FMA2(acc[4][0], q4, L.x, acc[4][0]); FMA2(acc[4][1], q4, L.y, acc[4][1]); \
        FMA2(acc[4][2], q4, H.x, acc[4][2]); FMA2(acc[4][3], q4, H.y, acc[4][3]); \
        FMA2(acc[5][0], q5, L.x, acc[5][0]); FMA2(acc[5][1], q5, L.y, acc[5][1]); \
        FMA2(acc[5][2], q5, H.x, acc[5][2]); FMA2(acc[5][3], q5, H.y, acc[5][3]); \
        FMA2(acc[6][0], q6, L.x, acc[6][0]); FMA2(acc[6][1], q6, L.y, acc[6][1]); \
        FMA2(acc[6][2], q6, H.x, acc[6][2]); FMA2(acc[6][3], q6, H.y, acc[6][3]); \
        FMA2(acc[7][0], q7, L.x, acc[7][0]); FMA2(acc[7][1], q7, L.y, acc[7][1]); \
        FMA2(acc[7][2], q7, H.x, acc[7][2]); FMA2(acc[7][3], q7, H.y, acc[7][3]); \
    }

    #pragma unroll 1
    for (int tt = 0; tt < 24; tt++) {
        STEP(0,  0, bva)
        STEP(32, 2, bvb)
        STEP(64, 4, bvc)
        j += 96;
        s += 6;
    }
#undef STEP

    // reduce + write 8 rows
    #pragma unroll
    for (int r = 0; r < 8; r++) {
        float f0, f1, f2, f3, f4, f5, f6, f7;
        unsigned u0, u1;
        UNPK2(u0, u1, acc[r][0]); f0 = __uint_as_float(u0); f1 = __uint_as_float(u1);
        UNPK2(u0, u1, acc[r][1]); f2 = __uint_as_float(u0); f3 = __uint_as_float(u1);
        UNPK2(u0, u1, acc[r][2]); f4 = __uint_as_float(u0); f5 = __uint_as_float(u1);
        UNPK2(u0, u1, acc[r][3]); f6 = __uint_as_float(u0); f7 = __uint_as_float(u1);
        #pragma unroll
        for (int off = 16; off; off >>= 1) {
            f0 += __shfl_xor_sync(0xffffffffu, f0, off);
            f1 += __shfl_xor_sync(0xffffffffu, f1, off);
            f2 += __shfl_xor_sync(0xffffffffu, f2, off);
            f3 += __shfl_xor_sync(0xffffffffu, f3, off);
            f4 += __shfl_xor_sync(0xffffffffu, f4, off);
            f5 += __shfl_xor_sync(0xffffffffu, f5, off);
            f6 += __shfl_xor_sync(0xffffffffu, f6, off);
            f7 += __shfl_xor_sync(0xffffffffu, f7, off);
        }
        float rr = f0;
        if (lane == 1) rr = f1;
        if (lane == 2) rr = f2;
        if (lane == 3) rr = f3;
        if (lane == 4) rr = f4;
        if (lane == 5) rr = f5;
        if (lane == 6) rr = f6;
        if (lane == 7) rr = f7;
        if (lane < 8)
            out[((size_t)(b * 64) + hd * 8 + lane) * HW + i0 + r] = rr / rsum[r];
    }
}

// ---------------- launch ----------------
extern "C" void kernel_launch(void* const* d_in, const int* in_sizes, int n_in,
                              void* d_out, int out_size) {
    const float* f    = (const float*)d_in[0];
    const float* wqkv = (const float*)d_in[1];
    const float* wq   = (const float*)d_in[2];
    const float* bq   = (const float*)d_in[3];
    const float* wk   = (const float*)d_in[4];
    const float* bk   = (const float*)d_in[5];
    const float* ph   = (const float*)d_in[6];
    const float* pw   = (const float*)d_in[7];
    float* out = (float*)d_out;

    qkv_kernel<<<144, 256>>>(f, wqkv);
    conv_kernel<<<512, 288>>>(wq, bq, wk, bk);
    attn_kernel<<<1152, 128>>>(ph, pw, out);
}

// round 12
// speedup vs baseline: 1.3711x; 1.0998x over previous
#include <cuda_runtime.h>
#include <math.h>
#include <stdint.h>

#define NB 2
#define NC 64
#define HW 2304
#define INNER 64
#define HEADS 8
#define DH 8
#define MM 36
#define SCALE 0.35355339059327373f

// ---------------- scratch (device globals; no allocation allowed) ----------------
__device__ float g_qt[NB * HW * INNER];          // q channel-last: [b][p][c]
__device__ float g_kt[NB * HW * INNER];          // k channel-last: [b][p][c]
__device__ float4 g_vlo4[NB * HEADS * HW];       // v channels 0..3:  [b][head][j]
__device__ float4 g_vhi4[NB * HEADS * HW];       // v channels 4..7
__device__ float g_qd[NB * INNER * MM];          // conv+gelu(q): [b][oc][pos36]
__device__ float g_kd[NB * INNER * MM];

// ---------------- kernel A: 1x1 conv qkv + layout transforms ----------------
// grid: 2 b * 72 ptiles(32) * 4 ochunks(48) = 576 blocks, 256 threads
__global__ void qkv_kernel(const float* __restrict__ f, const float* __restrict__ wqkv) {
    __shared__ float sF[64 * 32];   // [c][pp]
    int bid = blockIdx.x;
    int b = bid / 288;
    int rest = bid % 288;
    int p0  = (rest >> 2) * 32;
    int oc0 = (rest & 3) * 48;

    for (int idx = threadIdx.x; idx < 64 * 32; idx += 256) {
        int c = idx >> 5, pp = idx & 31;
        sF[idx] = f[(b * 64 + c) * HW + p0 + pp];
    }
    __syncthreads();

    int pp = threadIdx.x & 31;
    int warp = threadIdx.x >> 5;   // 0..7
    int p = p0 + pp;

    #pragma unroll
    for (int oo = 0; oo < 3; oo++) {
        int oA = oc0 + warp + 16 * oo;     // two o's per pass: oA, oA+8
        int oB = oA + 8;
        const float* w0 = wqkv + oA * 64;
        const float* w1 = wqkv + oB * 64;
        float a0 = 0.f, a1 = 0.f, a2 = 0.f, a3 = 0.f;
        float b0 = 0.f, b1 = 0.f, b2 = 0.f, b3 = 0.f;
        #pragma unroll
        for (int c = 0; c < 16; c++) {
            float v0 = sF[c * 32 + pp];
            float v1 = sF[(c + 16) * 32 + pp];
            float v2 = sF[(c + 32) * 32 + pp];
            float v3 = sF[(c + 48) * 32 + pp];
            a0 = fmaf(__ldg(&w0[c]),      v0, a0);
            a1 = fmaf(__ldg(&w0[c + 16]), v1, a1);
            a2 = fmaf(__ldg(&w0[c + 32]), v2, a2);
            a3 = fmaf(__ldg(&w0[c + 48]), v3, a3);
            b0 = fmaf(__ldg(&w1[c]),      v0, b0);
            b1 = fmaf(__ldg(&w1[c + 16]), v1, b1);
            b2 = fmaf(__ldg(&w1[c + 32]), v2, b2);
            b3 = fmaf(__ldg(&w1[c + 48]), v3, b3);
        }
        float accA = (a0 + a1) + (a2 + a3);
        float accB = (b0 + b1) + (b2 + b3);

        #pragma unroll
        for (int pick = 0; pick < 2; pick++) {
            int o = pick ? oB : oA;
            float acc = pick ? accB : accA;
            if (o < 64) {
                g_qt[(b * HW + p) * 64 + o] = acc;
            } else if (o < 128) {
                g_kt[(b * HW + p) * 64 + (o - 64)] = acc;
            } else {
                int oi = o - 128;
                int hd = oi >> 3, c = oi & 7;
                float* vout = (float*)(c < 4 ? g_vlo4 : g_vhi4);
                vout[((size_t)(b * HEADS + hd) * HW + p) * 4 + (c & 3)] = acc;
            }
        }
    }
}

// ---------------- kernel B: 11x11 stride-8 pad-2 conv + exact GELU ----------------
__global__ void conv_kernel(const float* __restrict__ wq, const float* __restrict__ bq,
                            const float* __restrict__ wk, const float* __restrict__ bk) {
    int bid = blockIdx.x;
    int half = bid & 1;
    int oc = (bid >> 1) & 63;
    int b  = (bid >> 7) & 1;
    int t  = bid >> 8;

    const float* wsrc = (t ? wk : wq) + oc * 64 * 121;   // layout [ic][tap], linear
    const float* in   = (t ? g_kt : g_qt) + b * HW * 64;

    __shared__ __align__(16) float sw[121 * 66];
    for (int idx = threadIdx.x; idx < 121 * 64; idx += 288) {
        int ic = idx / 121, tap = idx % 121;
        sw[tap * 66 + ic] = wsrc[idx];
    }
    __syncthreads();

    int warp = threadIdx.x >> 5, lane = threadIdx.x & 31;
    int pos0 = half * 18 + warp * 2;

    int oh0 = pos0 / 6, ow0 = pos0 % 6;
    int oh1 = (pos0 + 1) / 6, ow1 = (pos0 + 1) % 6;
    int ihb0 = oh0 * 8 - 2, iwb0 = ow0 * 8 - 2;
    int ihb1 = oh1 * 8 - 2, iwb1 = ow1 * 8 - 2;

    float2 a0 = {0.f, 0.f}, a1 = {0.f, 0.f};
    #pragma unroll
    for (int kh = 0; kh < 11; kh++) {
        #pragma unroll
        for (int kw = 0; kw < 11; kw++) {
            const float2* wp2 = (const float2*)(sw + (kh * 11 + kw) * 66);
            float2 wv = wp2[lane];
            int ih0 = ihb0 + kh, iw0 = iwb0 + kw;
            if ((unsigned)ih0 < 48u && (unsigned)iw0 < 48u) {
                const float2* ip = (const float2*)(in + (ih0 * 48 + iw0) * 64);
                float2 iv = ip[lane];
                a0.x = fmaf(iv.x, wv.x, a0.x);
                a0.y = fmaf(iv.y, wv.y, a0.y);
            }
            int ih1 = ihb1 + kh, iw1 = iwb1 + kw;
            if ((unsigned)ih1 < 48u && (unsigned)iw1 < 48u) {
                const float2* ip = (const float2*)(in + (ih1 * 48 + iw1) * 64);
                float2 iv = ip[lane];
                a1.x = fmaf(iv.x, wv.x, a1.x);
                a1.y = fmaf(iv.y, wv.y, a1.y);
            }
        }
    }
    float acc0 = a0.x + a0.y;
    float acc1 = a1.x + a1.y;
    #pragma unroll
    for (int off = 16; off; off >>= 1) {
        acc0 += __shfl_xor_sync(0xffffffffu, acc0, off);
        acc1 += __shfl_xor_sync(0xffffffffu, acc1, off);
    }
    if (lane == 0) {
        float bias = (t ? bk : bq)[oc];
        float* dst = (t ? g_kd : g_qd) + (b * 64 + oc) * MM;
        float x0 = acc0 + bias;
        dst[pos0] = 0.5f * x0 * (1.0f + erff(x0 * 0.7071067811865476f));
        float x1 = acc1 + bias;
        dst[pos0 + 1] = 0.5f * x1 * (1.0f + erff(x1 * 0.7071067811865476f));
    }
}

// ---------------- kernel D: fused dots + pos-logits + softmax + attn@v ----------------
// one warp per 8 consecutive output rows; grid 1152 blocks, 128 threads

#define FMA2(d, a, b, c) asm("fma.rn.f32x2 %0, %1, %2, %3;" : "=l"(d) : "l"(a), "l"(b), "l"(c))
#define PACK2(out, x)    asm("mov.b64 %0, {%1, %1};" : "=l"(out) : "r"(x))
#define UNPK2(lo, hi, in) asm("mov.b64 {%0, %1}, %2;" : "=r"(lo), "=r"(hi) : "l"(in))

// per-warp smem floats:
//  0    sQ[64]      (dead after sA/sB built; smB[24] aliased here)
//  64   sD[40]
//  104  sA[8*48]
//  488  sB[8*48]
//  872  eC2[144*8]  (layout [s][r], 16B-aligned)
//  2024 rsum[8]
#define WSH 2032

__global__ void __launch_bounds__(128, 4)
attn_kernel(const float* __restrict__ pos_h, const float* __restrict__ pos_w,
            float* __restrict__ out) {
    __shared__ float sh[4][WSH];
    int warp = threadIdx.x >> 5, lane = threadIdx.x & 31;
    int w = blockIdx.x * 4 + warp;              // global warp id < 4608
    int bh = w / 288;                           // 2304/8 = 288 row-groups per (b,h)
    int i0 = (w % 288) * 8;
    int b = bh >> 3, hd = bh & 7;

    float* sQ   = sh[warp];          // 64
    float* sD   = sh[warp] + 64;     // 40
    float* sA   = sh[warp] + 104;    // 8*48
    float* sB   = sh[warp] + 488;    // 8*48
    float* eC2  = sh[warp] + 872;    // 144*8, [s][r]
    float* rsum = sh[warp] + 2024;   // 8
    float* smB  = sh[warp];          // alias sQ: sumB16[r*3+phi], 24

    // stage q for 8 rows: sQ[r*8+c]
    {
        int t = lane;
        sQ[t] = g_qt[((size_t)(b * HW + i0 + (t >> 3))) * 64 + hd * 8 + (t & 7)];
        t += 32;
        sQ[t] = g_qt[((size_t)(b * HW + i0 + (t >> 3))) * 64 + hd * 8 + (t & 7)];
    }
    // inline dots: sD[t] = SCALE * sum_c qd[c][i36] * kd[c][t]   (i36 = i0>>6)
    {
        int i36 = i0 >> 6;
        const float* qd = g_qd + (b * 64 + hd * 8) * MM;
        const float* kd = g_kd + (b * 64 + hd * 8) * MM;
        for (int t = lane; t < 36; t += 32) {
            float s = 0.f;
            #pragma unroll
            for (int c = 0; c < 8; c++)
                s = fmaf(__ldg(&qd[c * MM + i36]), __ldg(&kd[c * MM + t]), s);
            sD[t] = s * SCALE;
        }
    }
    __syncwarp();

    // raw A/B for 8 rows
    for (int jh = lane; jh < 48; jh += 32) {
        float phv[8], pwv[8];
        #pragma unroll
        for (int c = 0; c < 8; c++) {
            phv[c] = __ldg(&pos_h[c * 48 + jh]);
            pwv[c] = __ldg(&pos_w[c * 48 + jh]);
        }
        #pragma unroll
        for (int r = 0; r < 8; r++) {
            float a = 0.f, bb = 0.f;
            #pragma unroll
            for (int c = 0; c < 8; c++) {
                float qv = sQ[r * 8 + c];
                a  = fmaf(qv, phv[c], a);
                bb = fmaf(qv, pwv[c], bb);
            }
            sA[r * 48 + jh] = a;
            sB[r * 48 + jh] = bb;
        }
    }
    __syncwarp();

    // per-component maxes
    float mA[8], mB[8], mD = -1e30f;
    #pragma unroll
    for (int r = 0; r < 8; r++) { mA[r] = -1e30f; mB[r] = -1e30f; }
    for (int t = lane; t < 48; t += 32) {
        #pragma unroll
        for (int r = 0; r < 8; r++) {
            mA[r] = fmaxf(mA[r], sA[r * 48 + t]);
            mB[r] = fmaxf(mB[r], sB[r * 48 + t]);
        }
    }
    for (int t = lane; t < 36; t += 32) mD = fmaxf(mD, sD[t]);
    #pragma unroll
    for (int off = 16; off; off >>= 1) {
        mD = fmaxf(mD, __shfl_xor_sync(0xffffffffu, mD, off));
        #pragma unroll
        for (int r = 0; r < 8; r++) {
            mA[r] = fmaxf(mA[r], __shfl_xor_sync(0xffffffffu, mA[r], off));
            mB[r] = fmaxf(mB[r], __shfl_xor_sync(0xffffffffu, mB[r], off));
        }
    }
    __syncwarp();

    // exponentiate in place
    for (int t = lane; t < 36; t += 32) sD[t] = __expf(sD[t] - mD);
    for (int t = lane; t < 48; t += 32) {
        #pragma unroll
        for (int r = 0; r < 8; r++) {
            sA[r * 48 + t] = __expf(sA[r * 48 + t] - mA[r]);
            sB[r * 48 + t] = __expf(sB[r * 48 + t] - mB[r]);
        }
    }
    __syncwarp();

    // eC2[s][r] = eA[r][s/3] * eD[s>>2]
    for (int s = lane; s < 144; s += 32) {
        float d = sD[s >> 2];
        int jh = s / 3;
        float4 v0, v1;
        v0.x = sA[0 * 48 + jh] * d;  v0.y = sA[1 * 48 + jh] * d;
        v0.z = sA[2 * 48 + jh] * d;  v0.w = sA[3 * 48 + jh] * d;
        v1.x = sA[4 * 48 + jh] * d;  v1.y = sA[5 * 48 + jh] * d;
        v1.z = sA[6 * 48 + jh] * d;  v1.w = sA[7 * 48 + jh] * d;
        *(float4*)&eC2[s * 8]     = v0;
        *(float4*)&eC2[s * 8 + 4] = v1;
    }
    __syncwarp();

    // register b-values: jw = (lane + 32t) % 48 has period 3 in t
    int w0 = lane;
    int w1 = (lane < 16) ? lane + 32 : lane - 16;
    int w2 = lane + 16;
    float bva[8], bvb[8], bvc[8];
    #pragma unroll
    for (int r = 0; r < 8; r++) {
        bva[r] = sB[r * 48 + w0];
        bvb[r] = sB[r * 48 + w1];
        bvc[r] = sB[r * 48 + w2];
    }

    // sumB16[r][phi] into smB (sQ dead)
    if (lane < 24) {
        int r = lane / 3, phi = lane % 3;
        float s16 = 0.f;
        #pragma unroll
        for (int u = 0; u < 16; u++) s16 += sB[r * 48 + phi * 16 + u];
        smB[r * 3 + phi] = s16;
    }
    __syncwarp();

    // row sums: ssum[r] = sum_s eC2[s][r] * sumB16[r][s%3]; reduce and park in rsum
    {
        float ssum[8] = {0.f, 0.f, 0.f, 0.f, 0.f, 0.f, 0.f, 0.f};
        for (int s = lane; s < 144; s += 32) {
            int phi = s % 3;
            float4 c0 = *(const float4*)&eC2[s * 8];
            float4 c1 = *(const float4*)&eC2[s * 8 + 4];
            ssum[0] = fmaf(c0.x, smB[0 + phi],  ssum[0]);
            ssum[1] = fmaf(c0.y, smB[3 + phi],  ssum[1]);
            ssum[2] = fmaf(c0.z, smB[6 + phi],  ssum[2]);
            ssum[3] = fmaf(c0.w, smB[9 + phi],  ssum[3]);
            ssum[4] = fmaf(c1.x, smB[12 + phi], ssum[4]);
            ssum[5] = fmaf(c1.y, smB[15 + phi], ssum[5]);
            ssum[6] = fmaf(c1.z, smB[18 + phi], ssum[6]);
            ssum[7] = fmaf(c1.w, smB[21 + phi], ssum[7]);
        }
        #pragma unroll
        for (int off = 16; off; off >>= 1) {
            #pragma unroll
            for (int r = 0; r < 8; r++)
                ssum[r] += __shfl_xor_sync(0xffffffffu, ssum[r], off);
        }
        if (lane == 0) {
            #pragma unroll
            for (int r = 0; r < 8; r++) rsum[r] = ssum[r];
        }
    }
    __syncwarp();

    const ulonglong2* vlo = (const ulonglong2*)g_vlo4 + (size_t)(b * HEADS + hd) * HW;
    const ulonglong2* vhi = (const ulonglong2*)g_vhi4 + (size_t)(b * HEADS + hd) * HW;

    unsigned long long acc[8][4];
    #pragma unroll
    for (int r = 0; r < 8; r++)
        #pragma unroll
        for (int k = 0; k < 4; k++) acc[r][k] = 0ull;

    // main loop: j = lane + 32t, t = 0..71; 3-phase unroll; s = (lane>>4) + 2t
    int j = lane;
    int s = lane >> 4;

#define STEP(JOFS, SOFS, BV) { \
        ulonglong2 L = vlo[j + (JOFS)]; \
        ulonglong2 H = vhi[j + (JOFS)]; \
        float4 c0 = *(const float4*)&eC2[(s + (SOFS)) * 8]; \
        float4 c1 = *(const float4*)&eC2[(s + (SOFS)) * 8 + 4]; \
        unsigned long long q0, q1, q2, q3, q4, q5, q6, q7; \
        PACK2(q0, __float_as_uint(c0.x * BV[0])); \
        PACK2(q1, __float_as_uint(c0.y * BV[1])); \
        PACK2(q2, __float_as_uint(c0.z * BV[2])); \
        PACK2(q3, __float_as_uint(c0.w * BV[3])); \
        PACK2(q4, __float_as_uint(c1.x * BV[4])); \
        PACK2(q5, __float_as_uint(c1.y * BV[5])); \
        PACK2(q6, __float_as_uint(c1.z * BV[6])); \
        PACK2(q7, __float_as_uint(c1.w * BV[7])); \
        FMA2(acc[0][0], q0, L.x, acc[0][0]); FMA2(acc[0][1], q0, L.y, acc[0][1]); \
        FMA2(acc[0][2], q0, H.x, acc[0][2]); FMA2(acc[0][3], q0, H.y, acc[0][3]); \
        FMA2(acc[1][0], q1, L.x, acc[1][0]); FMA2(acc[1][1], q1, L.y, acc[1][1]); \
        FMA2(acc[1][2], q1, H.x, acc[1][2]); FMA2(acc[1][3], q1, H.y, acc[1][3]); \
        FMA2(acc[2][0], q2, L.x, acc[2][0]); FMA2(acc[2][1], q2, L.y, acc[2][1]); \
        FMA2(acc[2][2], q2, H.x, acc[2][2]); FMA2(acc[2][3], q2, H.y, acc[2][3]); \
        FMA2(acc[3][0], q3, L.x, acc[3][0]); FMA2(acc[3][1], q3, L.y, acc[3][1]); \
        FMA2(acc[3][2], q3, H.x, acc[3][2]); FMA2(acc[3][3], q3, H.y, acc[3][3]); \
        FMA2(acc[4][0], q4, L.x, acc[4][0]); FMA2(acc[4][1], q4, L.y, acc[4][1]); \
        FMA2(acc[4][2], q4, H.x, acc[4][2]); FMA2(acc[4][3], q4, H.y, acc[4][3]); \
        FMA2(acc[5][0], q5, L.x, acc[5][0]); FMA2(acc[5][1], q5, L.y, acc[5][1]); \
        FMA2(acc[5][2], q5, H.x, acc[5][2]); FMA2(acc[5][3], q5, H.y, acc[5][3]); \
        FMA2(acc[6][0], q6, L.x, acc[6][0]); FMA2(acc[6][1], q6, L.y, acc[6][1]); \
        FMA2(acc[6][2], q6, H.x, acc[6][2]); FMA2(acc[6][3], q6, H.y, acc[6][3]); \
        FMA2(acc[7][0], q7, L.x, acc[7][0]); FMA2(acc[7][1], q7, L.y, acc[7][1]); \
        FMA2(acc[7][2], q7, H.x, acc[7][2]); FMA2(acc[7][3], q7, H.y, acc[7][3]); \
    }

    #pragma unroll 1
    for (int tt = 0; tt < 24; tt++) {
        STEP(0,  0, bva)
        STEP(32, 2, bvb)
        STEP(64, 4, bvc)
        j += 96;
        s += 6;
    }
#undef STEP

    // reduce + write 8 rows
    #pragma unroll
    for (int r = 0; r < 8; r++) {
        float f0, f1, f2, f3, f4, f5, f6, f7;
        unsigned u0, u1;
        UNPK2(u0, u1, acc[r][0]); f0 = __uint_as_float(u0); f1 = __uint_as_float(u1);
        UNPK2(u0, u1, acc[r][1]); f2 = __uint_as_float(u0); f3 = __uint_as_float(u1);
        UNPK2(u0, u1, acc[r][2]); f4 = __uint_as_float(u0); f5 = __uint_as_float(u1);
        UNPK2(u0, u1, acc[r][3]); f6 = __uint_as_float(u0); f7 = __uint_as_float(u1);
        #pragma unroll
        for (int off = 16; off; off >>= 1) {
            f0 += __shfl_xor_sync(0xffffffffu, f0, off);
            f1 += __shfl_xor_sync(0xffffffffu, f1, off);
            f2 += __shfl_xor_sync(0xffffffffu, f2, off);
            f3 += __shfl_xor_sync(0xffffffffu, f3, off);
            f4 += __shfl_xor_sync(0xffffffffu, f4, off);
            f5 += __shfl_xor_sync(0xffffffffu, f5, off);
            f6 += __shfl_xor_sync(0xffffffffu, f6, off);
            f7 += __shfl_xor_sync(0xffffffffu, f7, off);
        }
        float rr = f0;
        if (lane == 1) rr = f1;
        if (lane == 2) rr = f2;
        if (lane == 3) rr = f3;
        if (lane == 4) rr = f4;
        if (lane == 5) rr = f5;
        if (lane == 6) rr = f6;
        if (lane == 7) rr = f7;
        if (lane < 8)
            out[((size_t)(b * 64) + hd * 8 + lane) * HW + i0 + r] = rr / rsum[r];
    }
}

// ---------------- launch ----------------
extern "C" void kernel_launch(void* const* d_in, const int* in_sizes, int n_in,
                              void* d_out, int out_size) {
    const float* f    = (const float*)d_in[0];
    const float* wqkv = (const float*)d_in[1];
    const float* wq   = (const float*)d_in[2];
    const float* bq   = (const float*)d_in[3];
    const float* wk   = (const float*)d_in[4];
    const float* bk   = (const float*)d_in[5];
    const float* ph   = (const float*)d_in[6];
    const float* pw   = (const float*)d_in[7];
    float* out = (float*)d_out;

    qkv_kernel<<<576, 256>>>(f, wqkv);
    conv_kernel<<<512, 288>>>(wq, bq, wk, bk);
    attn_kernel<<<1152, 128>>>(ph, pw, out);
}

// round 13
// speedup vs baseline: 1.4597x; 1.0647x over previous
#include <cuda_runtime.h>
#include <math.h>
#include <stdint.h>

#define NB 2
#define NC 64
#define HW 2304
#define INNER 64
#define HEADS 8
#define DH 8
#define MM 36
#define SCALE 0.35355339059327373f

// ---------------- scratch (device globals; no allocation allowed) ----------------
__device__ float g_qt[NB * HW * INNER];          // q channel-last: [b][p][c]
__device__ float g_kt[NB * HW * INNER];          // k channel-last: [b][p][c]
__device__ float4 g_vlo4[NB * HEADS * HW];       // v channels 0..3:  [b][head][j]
__device__ float4 g_vhi4[NB * HEADS * HW];       // v channels 4..7
__device__ float g_qd[NB * INNER * MM];          // conv+gelu(q): [b][oc][pos36]
__device__ float g_kd[NB * INNER * MM];

// ---------------- kernel A: 1x1 conv qkv + layout transforms ----------------
// grid: 2 b * 72 ptiles(32) * 4 ochunks(48) = 576 blocks, 256 threads
// weights staged in smem; inner loop is LDS-only (broadcast LDS.128 for weights)
__global__ void qkv_kernel(const float* __restrict__ f, const float* __restrict__ wqkv) {
    __shared__ float sF[64 * 32];        // [c][pp]
    __shared__ float4 sW4[48 * 16];      // [oidx][c4] : 48 rows x 16 float4 (64 c)
    int bid = blockIdx.x;
    int b = bid / 288;
    int rest = bid % 288;
    int p0  = (rest >> 2) * 32;
    int oc0 = (rest & 3) * 48;

    for (int idx = threadIdx.x; idx < 64 * 32; idx += 256) {
        int c = idx >> 5, pp = idx & 31;
        sF[idx] = f[(b * 64 + c) * HW + p0 + pp];
    }
    {
        const float4* wsrc = (const float4*)(wqkv + oc0 * 64);   // linear 768 float4
        for (int idx = threadIdx.x; idx < 768; idx += 256)
            sW4[idx] = wsrc[idx];
    }
    __syncthreads();

    int pp = threadIdx.x & 31;
    int warp = threadIdx.x >> 5;   // 0..7, each warp owns 6 outputs
    int p = p0 + pp;

    float acc[6] = {0.f, 0.f, 0.f, 0.f, 0.f, 0.f};
    const float4* w = sW4 + (warp * 6) * 16;

    #pragma unroll 4
    for (int c4 = 0; c4 < 16; c4++) {
        float v0 = sF[(c4 * 4 + 0) * 32 + pp];
        float v1 = sF[(c4 * 4 + 1) * 32 + pp];
        float v2 = sF[(c4 * 4 + 2) * 32 + pp];
        float v3 = sF[(c4 * 4 + 3) * 32 + pp];
        #pragma unroll
        for (int k = 0; k < 6; k++) {
            float4 wv = w[k * 16 + c4];          // broadcast LDS.128
            acc[k] = fmaf(wv.x, v0, acc[k]);
            acc[k] = fmaf(wv.y, v1, acc[k]);
            acc[k] = fmaf(wv.z, v2, acc[k]);
            acc[k] = fmaf(wv.w, v3, acc[k]);
        }
    }

    #pragma unroll
    for (int k = 0; k < 6; k++) {
        int o = oc0 + warp * 6 + k;
        float a = acc[k];
        if (o < 64) {
            g_qt[(b * HW + p) * 64 + o] = a;
        } else if (o < 128) {
            g_kt[(b * HW + p) * 64 + (o - 64)] = a;
        } else {
            int oi = o - 128;
            int hd = oi >> 3, c = oi & 7;
            float* vout = (float*)(c < 4 ? g_vlo4 : g_vhi4);
            vout[((size_t)(b * HEADS + hd) * HW + p) * 4 + (c & 3)] = a;
        }
    }
}

// ---------------- kernel B: 11x11 stride-8 pad-2 conv + exact GELU ----------------
__global__ void conv_kernel(const float* __restrict__ wq, const float* __restrict__ bq,
                            const float* __restrict__ wk, const float* __restrict__ bk) {
    int bid = blockIdx.x;
    int half = bid & 1;
    int oc = (bid >> 1) & 63;
    int b  = (bid >> 7) & 1;
    int t  = bid >> 8;

    const float* wsrc = (t ? wk : wq) + oc * 64 * 121;   // layout [ic][tap], linear
    const float* in   = (t ? g_kt : g_qt) + b * HW * 64;

    __shared__ __align__(16) float sw[121 * 66];
    for (int idx = threadIdx.x; idx < 121 * 64; idx += 288) {
        int ic = idx / 121, tap = idx % 121;
        sw[tap * 66 + ic] = wsrc[idx];
    }
    __syncthreads();

    int warp = threadIdx.x >> 5, lane = threadIdx.x & 31;
    int pos0 = half * 18 + warp * 2;

    int oh0 = pos0 / 6, ow0 = pos0 % 6;
    int oh1 = (pos0 + 1) / 6, ow1 = (pos0 + 1) % 6;
    int ihb0 = oh0 * 8 - 2, iwb0 = ow0 * 8 - 2;
    int ihb1 = oh1 * 8 - 2, iwb1 = ow1 * 8 - 2;

    float2 a0 = {0.f, 0.f}, a1 = {0.f, 0.f};
    #pragma unroll
    for (int kh = 0; kh < 11; kh++) {
        #pragma unroll
        for (int kw = 0; kw < 11; kw++) {
            const float2* wp2 = (const float2*)(sw + (kh * 11 + kw) * 66);
            float2 wv = wp2[lane];
            int ih0 = ihb0 + kh, iw0 = iwb0 + kw;
            if ((unsigned)ih0 < 48u && (unsigned)iw0 < 48u) {
                const float2* ip = (const float2*)(in + (ih0 * 48 + iw0) * 64);
                float2 iv = ip[lane];
                a0.x = fmaf(iv.x, wv.x, a0.x);
                a0.y = fmaf(iv.y, wv.y, a0.y);
            }
            int ih1 = ihb1 + kh, iw1 = iwb1 + kw;
            if ((unsigned)ih1 < 48u && (unsigned)iw1 < 48u) {
                const float2* ip = (const float2*)(in + (ih1 * 48 + iw1) * 64);
                float2 iv = ip[lane];
                a1.x = fmaf(iv.x, wv.x, a1.x);
                a1.y = fmaf(iv.y, wv.y, a1.y);
            }
        }
    }
    float acc0 = a0.x + a0.y;
    float acc1 = a1.x + a1.y;
    #pragma unroll
    for (int off = 16; off; off >>= 1) {
        acc0 += __shfl_xor_sync(0xffffffffu, acc0, off);
        acc1 += __shfl_xor_sync(0xffffffffu, acc1, off);
    }
    if (lane == 0) {
        float bias = (t ? bk : bq)[oc];
        float* dst = (t ? g_kd : g_qd) + (b * 64 + oc) * MM;
        float x0 = acc0 + bias;
        dst[pos0] = 0.5f * x0 * (1.0f + erff(x0 * 0.7071067811865476f));
        float x1 = acc1 + bias;
        dst[pos0 + 1] = 0.5f * x1 * (1.0f + erff(x1 * 0.7071067811865476f));
    }
}

// ---------------- kernel D: fused dots + pos-logits + softmax + attn@v ----------------
// one warp per 8 consecutive output rows; grid 1152 blocks, 128 threads

#define FMA2(d, a, b, c) asm("fma.rn.f32x2 %0, %1, %2, %3;" : "=l"(d) : "l"(a), "l"(b), "l"(c))
#define PACK2(out, x)    asm("mov.b64 %0, {%1, %1};" : "=l"(out) : "r"(x))
#define UNPK2(lo, hi, in) asm("mov.b64 {%0, %1}, %2;" : "=r"(lo), "=r"(hi) : "l"(in))

// per-warp smem floats:
//  0    sQ[64]      (dead after sA/sB built; smB[24] aliased here)
//  64   sD[40]
//  104  sA[8*48]
//  488  sB[8*48]
//  872  eC2[144*8]  (layout [s][r], 16B-aligned)
//  2024 rsum[8]
#define WSH 2032

__global__ void __launch_bounds__(128, 4)
attn_kernel(const float* __restrict__ pos_h, const float* __restrict__ pos_w,
            float* __restrict__ out) {
    __shared__ float sh[4][WSH];
    int warp = threadIdx.x >> 5, lane = threadIdx.x & 31;
    int w = blockIdx.x * 4 + warp;              // global warp id < 4608
    int bh = w / 288;                           // 2304/8 = 288 row-groups per (b,h)
    int i0 = (w % 288) * 8;
    int b = bh >> 3, hd = bh & 7;

    float* sQ   = sh[warp];          // 64
    float* sD   = sh[warp] + 64;     // 40
    float* sA   = sh[warp] + 104;    // 8*48
    float* sB   = sh[warp] + 488;    // 8*48
    float* eC2  = sh[warp] + 872;    // 144*8, [s][r]
    float* rsum = sh[warp] + 2024;   // 8
    float* smB  = sh[warp];          // alias sQ: sumB16[r*3+phi], 24

    // stage q for 8 rows: sQ[r*8+c]
    {
        int t = lane;
        sQ[t] = g_qt[((size_t)(b * HW + i0 + (t >> 3))) * 64 + hd * 8 + (t & 7)];
        t += 32;
        sQ[t] = g_qt[((size_t)(b * HW + i0 + (t >> 3))) * 64 + hd * 8 + (t & 7)];
    }
    // inline dots: sD[t] = SCALE * sum_c qd[c][i36] * kd[c][t]   (i36 = i0>>6)
    {
        int i36 = i0 >> 6;
        const float* qd = g_qd + (b * 64 + hd * 8) * MM;
        const float* kd = g_kd + (b * 64 + hd * 8) * MM;
        for (int t = lane; t < 36; t += 32) {
            float s = 0.f;
            #pragma unroll
            for (int c = 0; c < 8; c++)
                s = fmaf(__ldg(&qd[c * MM + i36]), __ldg(&kd[c * MM + t]), s);
            sD[t] = s * SCALE;
        }
    }
    __syncwarp();

    // raw A/B for 8 rows
    for (int jh = lane; jh < 48; jh += 32) {
        float phv[8], pwv[8];
        #pragma unroll
        for (int c = 0; c < 8; c++) {
            phv[c] = __ldg(&pos_h[c * 48 + jh]);
            pwv[c] = __ldg(&pos_w[c * 48 + jh]);
        }
        #pragma unroll
        for (int r = 0; r < 8; r++) {
            float a = 0.f, bb = 0.f;
            #pragma unroll
            for (int c = 0; c < 8; c++) {
                float qv = sQ[r * 8 + c];
                a  = fmaf(qv, phv[c], a);
                bb = fmaf(qv, pwv[c], bb);
            }
            sA[r * 48 + jh] = a;
            sB[r * 48 + jh] = bb;
        }
    }
    __syncwarp();

    // per-component maxes
    float mA[8], mB[8], mD = -1e30f;
    #pragma unroll
    for (int r = 0; r < 8; r++) { mA[r] = -1e30f; mB[r] = -1e30f; }
    for (int t = lane; t < 48; t += 32) {
        #pragma unroll
        for (int r = 0; r < 8; r++) {
            mA[r] = fmaxf(mA[r], sA[r * 48 + t]);
            mB[r] = fmaxf(mB[r], sB[r * 48 + t]);
        }
    }
    for (int t = lane; t < 36; t += 32) mD = fmaxf(mD, sD[t]);
    #pragma unroll
    for (int off = 16; off; off >>= 1) {
        mD = fmaxf(mD, __shfl_xor_sync(0xffffffffu, mD, off));
        #pragma unroll
        for (int r = 0; r < 8; r++) {
            mA[r] = fmaxf(mA[r], __shfl_xor_sync(0xffffffffu, mA[r], off));
            mB[r] = fmaxf(mB[r], __shfl_xor_sync(0xffffffffu, mB[r], off));
        }
    }
    __syncwarp();

    // exponentiate in place
    for (int t = lane; t < 36; t += 32) sD[t] = __expf(sD[t] - mD);
    for (int t = lane; t < 48; t += 32) {
        #pragma unroll
        for (int r = 0; r < 8; r++) {
            sA[r * 48 + t] = __expf(sA[r * 48 + t] - mA[r]);
            sB[r * 48 + t] = __expf(sB[r * 48 + t] - mB[r]);
        }
    }
    __syncwarp();

    // eC2[s][r] = eA[r][s/3] * eD[s>>2]
    for (int s = lane; s < 144; s += 32) {
        float d = sD[s >> 2];
        int jh = s / 3;
        float4 v0, v1;
        v0.x = sA[0 * 48 + jh] * d;  v0.y = sA[1 * 48 + jh] * d;
        v0.z = sA[2 * 48 + jh] * d;  v0.w = sA[3 * 48 + jh] * d;
        v1.x = sA[4 * 48 + jh] * d;  v1.y = sA[5 * 48 + jh] * d;
        v1.z = sA[6 * 48 + jh] * d;  v1.w = sA[7 * 48 + jh] * d;
        *(float4*)&eC2[s * 8]     = v0;
        *(float4*)&eC2[s * 8 + 4] = v1;
    }
    __syncwarp();

    // register b-values: jw = (lane + 32t) % 48 has period 3 in t
    int w0 = lane;
    int w1 = (lane < 16) ? lane + 32 : lane - 16;
    int w2 = lane + 16;
    float bva[8], bvb[8], bvc[8];
    #pragma unroll
    for (int r = 0; r < 8; r++) {
        bva[r] = sB[r * 48 + w0];
        bvb[r] = sB[r * 48 + w1];
        bvc[r] = sB[r * 48 + w2];
    }

    // sumB16[r][phi] into smB (sQ dead)
    if (lane < 24) {
        int r = lane / 3, phi = lane % 3;
        float s16 = 0.f;
        #pragma unroll
        for (int u = 0; u < 16; u++) s16 += sB[r * 48 + phi * 16 + u];
        smB[r * 3 + phi] = s16;
    }
    __syncwarp();

    // row sums: ssum[r] = sum_s eC2[s][r] * sumB16[r][s%3]; reduce and park in rsum
    {
        float ssum[8] = {0.f, 0.f, 0.f, 0.f, 0.f, 0.f, 0.f, 0.f};
        for (int s = lane; s < 144; s += 32) {
            int phi = s % 3;
            float4 c0 = *(const float4*)&eC2[s * 8];
            float4 c1 = *(const float4*)&eC2[s * 8 + 4];
            ssum[0] = fmaf(c0.x, smB[0 + phi],  ssum[0]);
            ssum[1] = fmaf(c0.y, smB[3 + phi],  ssum[1]);
            ssum[2] = fmaf(c0.z, smB[6 + phi],  ssum[2]);
            ssum[3] = fmaf(c0.w, smB[9 + phi],  ssum[3]);
            ssum[4] = fmaf(c1.x, smB[12 + phi], ssum[4]);
            ssum[5] = fmaf(c1.y, smB[15 + phi], ssum[5]);
            ssum[6] = fmaf(c1.z, smB[18 + phi], ssum[6]);
            ssum[7] = fmaf(c1.w, smB[21 + phi], ssum[7]);
        }
        #pragma unroll
        for (int off = 16; off; off >>= 1) {
            #pragma unroll
            for (int r = 0; r < 8; r++)
                ssum[r] += __shfl_xor_sync(0xffffffffu, ssum[r], off);
        }
        if (lane == 0) {
            #pragma unroll
            for (int r = 0; r < 8; r++) rsum[r] = ssum[r];
        }
    }
    __syncwarp();

    const ulonglong2* vlo = (const ulonglong2*)g_vlo4 + (size_t)(b * HEADS + hd) * HW;
    const ulonglong2* vhi = (const ulonglong2*)g_vhi4 + (size_t)(b * HEADS + hd) * HW;

    unsigned long long acc[8][4];
    #pragma unroll
    for (int r = 0; r < 8; r++)
        #pragma unroll
        for (int k = 0; k < 4; k++) acc[r][k] = 0ull;

    // main loop: j = lane + 32t, t = 0..71; 3-phase unroll; s = (lane>>4) + 2t
    int j = lane;
    int s = lane >> 4;

#define STEP(JOFS, SOFS, BV) { \
        ulonglong2 L = vlo[j + (JOFS)]; \
        ulonglong2 H = vhi[j + (JOFS)]; \
        float4 c0 = *(const float4*)&eC2[(s + (SOFS)) * 8]; \
        float4 c1 = *(const float4*)&eC2[(s + (SOFS)) * 8 + 4]; \
        unsigned long long q0, q1, q2, q3, q4, q5, q6, q7; \
        PACK2(q0, __float_as_uint(c0.x * BV[0])); \
        PACK2(q1, __float_as_uint(c0.y * BV[1])); \
        PACK2(q2, __float_as_uint(c0.z * BV[2])); \
        PACK2(q3, __float_as_uint(c0.w * BV[3])); \
        PACK2(q4, __float_as_uint(c1.x * BV[4])); \
        PACK2(q5, __float_as_uint(c1.y * BV[5])); \
        PACK2(q6, __float_as_uint(c1.z * BV[6])); \
        PACK2(q7, __float_as_uint(c1.w * BV[7])); \
        FMA2(acc[0][0], q0, L.x, acc[0][0]); FMA2(acc[0][1], q0, L.y, acc[0][1]); \
        FMA2(acc[0][2], q0, H.x, acc[0][2]); FMA2(acc[0][3], q0, H.y, acc[0][3]); \
        FMA2(acc[1][0], q1, L.x, acc[1][0]); FMA2(acc[1][1], q1, L.y, acc[1][1]); \
        FMA2(acc[1][2], q1, H.x, acc[1][2]); FMA2(acc[1][3], q1, H.y, acc[1][3]); \
        FMA2(acc[2][0], q2, L.x, acc[2][0]); FMA2(acc[2][1], q2, L.y, acc[2][1]); \
        FMA2(acc[2][2], q2, H.x, acc[2][2]); FMA2(acc[2][3], q2, H.y, acc[2][3]); \
        FMA2(acc[3][0], q3, L.x, acc[3][0]); FMA2(acc[3][1], q3, L.y, acc[3][1]); \
        FMA2(acc[3][2], q3, H.x, acc[3][2]); FMA2(acc[3][3], q3, H.y, acc[3][3]); \
        FMA2(acc[4][0], q4, L.x, acc[4][0]); FMA2(acc[4][1], q4, L.y, acc[4][1]); \
        FMA2(acc[4][2], q4, H.x, acc[4][2]); FMA2(acc[4][3], q4, H.y, acc[4][3]); \
        FMA2(acc[5][0], q5, L.x, acc[5][0]); FMA2(acc[5][1], q5, L.y, acc[5][1]); \
        FMA2(acc[5][2], q5, H.x, acc[5][2]); FMA2(acc[5][3], q5, H.y, acc[5][3]); \
        FMA2(acc[6][0], q6, L.x, acc[6][0]); FMA2(acc[6][1], q6, L.y, acc[6][1]); \
        FMA2(acc[6][2], q6, H.x, acc[6][2]); FMA2(acc[6][3], q6, H.y, acc[6][3]); \
        FMA2(acc[7][0], q7, L.x, acc[7][0]); FMA2(acc[7][1], q7, L.y, acc[7][1]); \
        FMA2(acc[7][2], q7, H.x, acc[7][2]); FMA2(acc[7][3], q7, H.y, acc[7][3]); \
    }

    #pragma unroll 1
    for (int tt = 0; tt < 24; tt++) {
        STEP(0,  0, bva)
        STEP(32, 2, bvb)
        STEP(64, 4, bvc)
        j += 96;
        s += 6;
    }
#undef STEP

    // reduce + write 8 rows
    #pragma unroll
    for (int r = 0; r < 8; r++) {
        float f0, f1, f2, f3, f4, f5, f6, f7;
        unsigned u0, u1;
        UNPK2(u0, u1, acc[r][0]); f0 = __uint_as_float(u0); f1 = __uint_as_float(u1);
        UNPK2(u0, u1, acc[r][1]); f2 = __uint_as_float(u0); f3 = __uint_as_float(u1);
        UNPK2(u0, u1, acc[r][2]); f4 = __uint_as_float(u0); f5 = __uint_as_float(u1);
        UNPK2(u0, u1, acc[r][3]); f6 = __uint_as_float(u0); f7 = __uint_as_float(u1);
        #pragma unroll
        for (int off = 16; off; off >>= 1) {
            f0 += __shfl_xor_sync(0xffffffffu, f0, off);
            f1 += __shfl_xor_sync(0xffffffffu, f1, off);
            f2 += __shfl_xor_sync(0xffffffffu, f2, off);
            f3 += __shfl_xor_sync(0xffffffffu, f3, off);
            f4 += __shfl_xor_sync(0xffffffffu, f4, off);
            f5 += __shfl_xor_sync(0xffffffffu, f5, off);
            f6 += __shfl_xor_sync(0xffffffffu, f6, off);
            f7 += __shfl_xor_sync(0xffffffffu, f7, off);
        }
        float rr = f0;
        if (lane == 1) rr = f1;
        if (lane == 2) rr = f2;
        if (lane == 3) rr = f3;
        if (lane == 4) rr = f4;
        if (lane == 5) rr = f5;
        if (lane == 6) rr = f6;
        if (lane == 7) rr = f7;
        if (lane < 8)
            out[((size_t)(b * 64) + hd * 8 + lane) * HW + i0 + r] = rr / rsum[r];
    }
}

// ---------------- launch ----------------
extern "C" void kernel_launch(void* const* d_in, const int* in_sizes, int n_in,
                              void* d_out, int out_size) {
    const float* f    = (const float*)d_in[0];
    const float* wqkv = (const float*)d_in[1];
    const float* wq   = (const float*)d_in[2];
    const float* bq   = (const float*)d_in[3];
    const float* wk   = (const float*)d_in[4];
    const float* bk   = (const float*)d_in[5];
    const float* ph   = (const float*)d_in[6];
    const float* pw   = (const float*)d_in[7];
    float* out = (float*)d_out;

    qkv_kernel<<<576, 256>>>(f, wqkv);
    conv_kernel<<<512, 288>>>(wq, bq, wk, bk);
    attn_kernel<<<1152, 128>>>(ph, pw, out);
}

// round 14
// speedup vs baseline: 1.5584x; 1.0676x over previous
#include <cuda_runtime.h>
#include <math.h>
#include <stdint.h>

#define NB 2
#define NC 64
#define HW 2304
#define INNER 64
#define HEADS 8
#define DH 8
#define MM 36
#define SCALE 0.35355339059327373f

// ---------------- scratch (device globals; no allocation allowed) ----------------
__device__ float g_qt[NB * HW * INNER];          // q channel-last: [b][p][c]
__device__ float g_kt[NB * HW * INNER];          // k channel-last: [b][p][c]
__device__ float4 g_vlo4[NB * HEADS * HW];       // v channels 0..3:  [b][head][j]
__device__ float4 g_vhi4[NB * HEADS * HW];       // v channels 4..7
__device__ float g_qd[NB * INNER * MM];          // conv+gelu(q): [b][oc][pos36]
__device__ float g_kd[NB * INNER * MM];

// ---------------- kernel A: 1x1 conv qkv + layout transforms ----------------
// grid: 2 b * 72 ptiles(32) * 8 ochunks(24) = 1152 blocks, 256 threads
// LDS-only inner loop; coalesced epilogue via smem staging
__global__ void qkv_kernel(const float* __restrict__ f, const float* __restrict__ wqkv) {
    __shared__ float sF[64 * 32];        // [c][pp]
    __shared__ float4 sW4[24 * 16];      // [oidx][c4]
    __shared__ float sOut[32 * 25];      // [pp][oidx], pad 25
    int bid = blockIdx.x;
    int b = bid / 576;
    int rest = bid % 576;
    int p0  = (rest >> 3) * 32;
    int oc0 = (rest & 7) * 24;

    for (int idx = threadIdx.x; idx < 64 * 32; idx += 256) {
        int c = idx >> 5, pp = idx & 31;
        sF[idx] = f[(b * 64 + c) * HW + p0 + pp];
    }
    {
        const float4* wsrc = (const float4*)(wqkv + oc0 * 64);   // linear 384 float4
        for (int idx = threadIdx.x; idx < 384; idx += 256)
            sW4[idx] = wsrc[idx];
    }
    __syncthreads();

    int pp = threadIdx.x & 31;
    int warp = threadIdx.x >> 5;   // 0..7, each warp owns 3 outputs

    float acc0 = 0.f, acc1 = 0.f, acc2 = 0.f;
    const float4* w = sW4 + (warp * 3) * 16;

    #pragma unroll 4
    for (int c4 = 0; c4 < 16; c4++) {
        float v0 = sF[(c4 * 4 + 0) * 32 + pp];
        float v1 = sF[(c4 * 4 + 1) * 32 + pp];
        float v2 = sF[(c4 * 4 + 2) * 32 + pp];
        float v3 = sF[(c4 * 4 + 3) * 32 + pp];
        float4 w0 = w[c4];
        float4 w1 = w[16 + c4];
        float4 w2 = w[32 + c4];
        acc0 = fmaf(w0.x, v0, acc0); acc1 = fmaf(w1.x, v0, acc1); acc2 = fmaf(w2.x, v0, acc2);
        acc0 = fmaf(w0.y, v1, acc0); acc1 = fmaf(w1.y, v1, acc1); acc2 = fmaf(w2.y, v1, acc2);
        acc0 = fmaf(w0.z, v2, acc0); acc1 = fmaf(w1.z, v2, acc1); acc2 = fmaf(w2.z, v2, acc2);
        acc0 = fmaf(w0.w, v3, acc0); acc1 = fmaf(w1.w, v3, acc1); acc2 = fmaf(w2.w, v3, acc2);
    }

    // stage results: sOut[pp][warp*3 + k]   (stride 25 odd -> conflict-free)
    sOut[pp * 25 + warp * 3 + 0] = acc0;
    sOut[pp * 25 + warp * 3 + 1] = acc1;
    sOut[pp * 25 + warp * 3 + 2] = acc2;
    __syncthreads();

    // coalesced store: idx -> (p_local, oi), consecutive lanes = consecutive oi
    for (int idx = threadIdx.x; idx < 32 * 24; idx += 256) {
        int p_local = idx / 24;
        int oi = idx % 24;
        int o = oc0 + oi;
        int p = p0 + p_local;
        float a = sOut[p_local * 25 + oi];
        if (o < 64) {
            g_qt[(b * HW + p) * 64 + o] = a;
        } else if (o < 128) {
            g_kt[(b * HW + p) * 64 + (o - 64)] = a;
        } else {
            int oi2 = o - 128;
            int hd = oi2 >> 3, c = oi2 & 7;
            float* vout = (float*)(c < 4 ? g_vlo4 : g_vhi4);
            vout[((size_t)(b * HEADS + hd) * HW + p) * 4 + (c & 3)] = a;
        }
    }
}

// ---------------- kernel B: 11x11 stride-8 pad-2 conv + exact GELU ----------------
__global__ void conv_kernel(const float* __restrict__ wq, const float* __restrict__ bq,
                            const float* __restrict__ wk, const float* __restrict__ bk) {
    int bid = blockIdx.x;
    int half = bid & 1;
    int oc = (bid >> 1) & 63;
    int b  = (bid >> 7) & 1;
    int t  = bid >> 8;

    const float* wsrc = (t ? wk : wq) + oc * 64 * 121;   // layout [ic][tap], linear
    const float* in   = (t ? g_kt : g_qt) + b * HW * 64;

    __shared__ __align__(16) float sw[121 * 66];
    for (int idx = threadIdx.x; idx < 121 * 64; idx += 288) {
        int ic = idx / 121, tap = idx % 121;
        sw[tap * 66 + ic] = wsrc[idx];
    }
    __syncthreads();

    int warp = threadIdx.x >> 5, lane = threadIdx.x & 31;
    int pos0 = half * 18 + warp * 2;

    int oh0 = pos0 / 6, ow0 = pos0 % 6;
    int oh1 = (pos0 + 1) / 6, ow1 = (pos0 + 1) % 6;
    int ihb0 = oh0 * 8 - 2, iwb0 = ow0 * 8 - 2;
    int ihb1 = oh1 * 8 - 2, iwb1 = ow1 * 8 - 2;

    float2 a0 = {0.f, 0.f}, a1 = {0.f, 0.f};
    #pragma unroll
    for (int kh = 0; kh < 11; kh++) {
        #pragma unroll
        for (int kw = 0; kw < 11; kw++) {
            const float2* wp2 = (const float2*)(sw + (kh * 11 + kw) * 66);
            float2 wv = wp2[lane];
            int ih0 = ihb0 + kh, iw0 = iwb0 + kw;
            if ((unsigned)ih0 < 48u && (unsigned)iw0 < 48u) {
                const float2* ip = (const float2*)(in + (ih0 * 48 + iw0) * 64);
                float2 iv = ip[lane];
                a0.x = fmaf(iv.x, wv.x, a0.x);
                a0.y = fmaf(iv.y, wv.y, a0.y);
            }
            int ih1 = ihb1 + kh, iw1 = iwb1 + kw;
            if ((unsigned)ih1 < 48u && (unsigned)iw1 < 48u) {
                const float2* ip = (const float2*)(in + (ih1 * 48 + iw1) * 64);
                float2 iv = ip[lane];
                a1.x = fmaf(iv.x, wv.x, a1.x);
                a1.y = fmaf(iv.y, wv.y, a1.y);
            }
        }
    }
    float acc0 = a0.x + a0.y;
    float acc1 = a1.x + a1.y;
    #pragma unroll
    for (int off = 16; off; off >>= 1) {
        acc0 += __shfl_xor_sync(0xffffffffu, acc0, off);
        acc1 += __shfl_xor_sync(0xffffffffu, acc1, off);
    }
    if (lane == 0) {
        float bias = (t ? bk : bq)[oc];
        float* dst = (t ? g_kd : g_qd) + (b * 64 + oc) * MM;
        float x0 = acc0 + bias;
        dst[pos0] = 0.5f * x0 * (1.0f + erff(x0 * 0.7071067811865476f));
        float x1 = acc1 + bias;
        dst[pos0 + 1] = 0.5f * x1 * (1.0f + erff(x1 * 0.7071067811865476f));
    }
}

// ---------------- kernel D: fused dots + pos-logits + softmax + attn@v ----------------
// one warp per 8 consecutive output rows; grid 1152 blocks, 128 threads

#define FMA2(d, a, b, c) asm("fma.rn.f32x2 %0, %1, %2, %3;" : "=l"(d) : "l"(a), "l"(b), "l"(c))
#define PACK2(out, x)    asm("mov.b64 %0, {%1, %1};" : "=l"(out) : "r"(x))
#define UNPK2(lo, hi, in) asm("mov.b64 {%0, %1}, %2;" : "=r"(lo), "=r"(hi) : "l"(in))

// per-warp smem floats:
//  0    sQ[64]      (dead after sA/sB built; smB[24] aliased here)
//  64   sD[40]
//  104  sA[8*48]
//  488  sB[8*48]
//  872  eC2[144*8]  (layout [s][r], 16B-aligned)
//  2024 rsum[8]
#define WSH 2032

__global__ void __launch_bounds__(128, 4)
attn_kernel(const float* __restrict__ pos_h, const float* __restrict__ pos_w,
            float* __restrict__ out) {
    __shared__ float sh[4][WSH];
    int warp = threadIdx.x >> 5, lane = threadIdx.x & 31;
    int w = blockIdx.x * 4 + warp;              // global warp id < 4608
    int bh = w / 288;                           // 2304/8 = 288 row-groups per (b,h)
    int i0 = (w % 288) * 8;
    int b = bh >> 3, hd = bh & 7;

    float* sQ   = sh[warp];          // 64
    float* sD   = sh[warp] + 64;     // 40
    float* sA   = sh[warp] + 104;    // 8*48
    float* sB   = sh[warp] + 488;    // 8*48
    float* eC2  = sh[warp] + 872;    // 144*8, [s][r]
    float* rsum = sh[warp] + 2024;   // 8
    float* smB  = sh[warp];          // alias sQ: sumB16[r*3+phi], 24

    // stage q for 8 rows: sQ[r*8+c]
    {
        int t = lane;
        sQ[t] = g_qt[((size_t)(b * HW + i0 + (t >> 3))) * 64 + hd * 8 + (t & 7)];
        t += 32;
        sQ[t] = g_qt[((size_t)(b * HW + i0 + (t >> 3))) * 64 + hd * 8 + (t & 7)];
    }
    // inline dots: sD[t] = SCALE * sum_c qd[c][i36] * kd[c][t]   (i36 = i0>>6)
    {
        int i36 = i0 >> 6;
        const float* qd = g_qd + (b * 64 + hd * 8) * MM;
        const float* kd = g_kd + (b * 64 + hd * 8) * MM;
        for (int t = lane; t < 36; t += 32) {
            float s = 0.f;
            #pragma unroll
            for (int c = 0; c < 8; c++)
                s = fmaf(__ldg(&qd[c * MM + i36]), __ldg(&kd[c * MM + t]), s);
            sD[t] = s * SCALE;
        }
    }
    __syncwarp();

    // raw A/B for 8 rows
    for (int jh = lane; jh < 48; jh += 32) {
        float phv[8], pwv[8];
        #pragma unroll
        for (int c = 0; c < 8; c++) {
            phv[c] = __ldg(&pos_h[c * 48 + jh]);
            pwv[c] = __ldg(&pos_w[c * 48 + jh]);
        }
        #pragma unroll
        for (int r = 0; r < 8; r++) {
            float a = 0.f, bb = 0.f;
            #pragma unroll
            for (int c = 0; c < 8; c++) {
                float qv = sQ[r * 8 + c];
                a  = fmaf(qv, phv[c], a);
                bb = fmaf(qv, pwv[c], bb);
            }
            sA[r * 48 + jh] = a;
            sB[r * 48 + jh] = bb;
        }
    }
    __syncwarp();

    // per-component maxes
    float mA[8], mB[8], mD = -1e30f;
    #pragma unroll
    for (int r = 0; r < 8; r++) { mA[r] = -1e30f; mB[r] = -1e30f; }
    for (int t = lane; t < 48; t += 32) {
        #pragma unroll
        for (int r = 0; r < 8; r++) {
            mA[r] = fmaxf(mA[r], sA[r * 48 + t]);
            mB[r] = fmaxf(mB[r], sB[r * 48 + t]);
        }
    }
    for (int t = lane; t < 36; t += 32) mD = fmaxf(mD, sD[t]);
    #pragma unroll
    for (int off = 16; off; off >>= 1) {
        mD = fmaxf(mD, __shfl_xor_sync(0xffffffffu, mD, off));
        #pragma unroll
        for (int r = 0; r < 8; r++) {
            mA[r] = fmaxf(mA[r], __shfl_xor_sync(0xffffffffu, mA[r], off));
            mB[r] = fmaxf(mB[r], __shfl_xor_sync(0xffffffffu, mB[r], off));
        }
    }
    __syncwarp();

    // exponentiate in place
    for (int t = lane; t < 36; t += 32) sD[t] = __expf(sD[t] - mD);
    for (int t = lane; t < 48; t += 32) {
        #pragma unroll
        for (int r = 0; r < 8; r++) {
            sA[r * 48 + t] = __expf(sA[r * 48 + t] - mA[r]);
            sB[r * 48 + t] = __expf(sB[r * 48 + t] - mB[r]);
        }
    }
    __syncwarp();

    // eC2[s][r] = eA[r][s/3] * eD[s>>2]
    for (int s = lane; s < 144; s += 32) {
        float d = sD[s >> 2];
        int jh = s / 3;
        float4 v0, v1;
        v0.x = sA[0 * 48 + jh] * d;  v0.y = sA[1 * 48 + jh] * d;
        v0.z = sA[2 * 48 + jh] * d;  v0.w = sA[3 * 48 + jh] * d;
        v1.x = sA[4 * 48 + jh] * d;  v1.y = sA[5 * 48 + jh] * d;
        v1.z = sA[6 * 48 + jh] * d;  v1.w = sA[7 * 48 + jh] * d;
        *(float4*)&eC2[s * 8]     = v0;
        *(float4*)&eC2[s * 8 + 4] = v1;
    }
    __syncwarp();

    // register b-values: jw = (lane + 32t) % 48 has period 3 in t
    int w0 = lane;
    int w1 = (lane < 16) ? lane + 32 : lane - 16;
    int w2 = lane + 16;
    float bva[8], bvb[8], bvc[8];
    #pragma unroll
    for (int r = 0; r < 8; r++) {
        bva[r] = sB[r * 48 + w0];
        bvb[r] = sB[r * 48 + w1];
        bvc[r] = sB[r * 48 + w2];
    }

    // sumB16[r][phi] into smB (sQ dead)
    if (lane < 24) {
        int r = lane / 3, phi = lane % 3;
        float s16 = 0.f;
        #pragma unroll
        for (int u = 0; u < 16; u++) s16 += sB[r * 48 + phi * 16 + u];
        smB[r * 3 + phi] = s16;
    }
    __syncwarp();

    // row sums: ssum[r] = sum_s eC2[s][r] * sumB16[r][s%3]; reduce and park in rsum
    {
        float ssum[8] = {0.f, 0.f, 0.f, 0.f, 0.f, 0.f, 0.f, 0.f};
        for (int s = lane; s < 144; s += 32) {
            int phi = s % 3;
            float4 c0 = *(const float4*)&eC2[s * 8];
            float4 c1 = *(const float4*)&eC2[s * 8 + 4];
            ssum[0] = fmaf(c0.x, smB[0 + phi],  ssum[0]);
            ssum[1] = fmaf(c0.y, smB[3 + phi],  ssum[1]);
            ssum[2] = fmaf(c0.z, smB[6 + phi],  ssum[2]);
            ssum[3] = fmaf(c0.w, smB[9 + phi],  ssum[3]);
            ssum[4] = fmaf(c1.x, smB[12 + phi], ssum[4]);
            ssum[5] = fmaf(c1.y, smB[15 + phi], ssum[5]);
            ssum[6] = fmaf(c1.z, smB[18 + phi], ssum[6]);
            ssum[7] = fmaf(c1.w, smB[21 + phi], ssum[7]);
        }
        #pragma unroll
        for (int off = 16; off; off >>= 1) {
            #pragma unroll
            for (int r = 0; r < 8; r++)
                ssum[r] += __shfl_xor_sync(0xffffffffu, ssum[r], off);
        }
        if (lane == 0) {
            #pragma unroll
            for (int r = 0; r < 8; r++) rsum[r] = ssum[r];
        }
    }
    __syncwarp();

    const ulonglong2* vlo = (const ulonglong2*)g_vlo4 + (size_t)(b * HEADS + hd) * HW;
    const ulonglong2* vhi = (const ulonglong2*)g_vhi4 + (size_t)(b * HEADS + hd) * HW;

    unsigned long long acc[8][4];
    #pragma unroll
    for (int r = 0; r < 8; r++)
        #pragma unroll
        for (int k = 0; k < 4; k++) acc[r][k] = 0ull;

    // main loop: j = lane + 32t, t = 0..71; 3-phase unroll; s = (lane>>4) + 2t
    int j = lane;
    int s = lane >> 4;

#define STEP(JOFS, SOFS, BV) { \
        ulonglong2 L = vlo[j + (JOFS)]; \
        ulonglong2 H = vhi[j + (JOFS)]; \
        float4 c0 = *(const float4*)&eC2[(s + (SOFS)) * 8]; \
        float4 c1 = *(const float4*)&eC2[(s + (SOFS)) * 8 + 4]; \
        unsigned long long q0, q1, q2, q3, q4, q5, q6, q7; \
        PACK2(q0, __float_as_uint(c0.x * BV[0])); \
        PACK2(q1, __float_as_uint(c0.y * BV[1])); \
        PACK2(q2, __float_as_uint(c0.z * BV[2])); \
        PACK2(q3, __float_as_uint(c0.w * BV[3])); \
        PACK2(q4, __float_as_uint(c1.x * BV[4])); \
        PACK2(q5, __float_as_uint(c1.y * BV[5])); \
        PACK2(q6, __float_as_uint(c1.z * BV[6])); \
        PACK2(q7, __float_as_uint(c1.w * BV[7])); \
        FMA2(acc[0][0], q0, L.x, acc[0][0]); FMA2(acc[0][1], q0, L.y, acc[0][1]); \
        FMA2(acc[0][2], q0, H.x, acc[0][2]); FMA2(acc[0][3], q0, H.y, acc[0][3]); \
        FMA2(acc[1][0], q1, L.x, acc[1][0]); FMA2(acc[1][1], q1, L.y, acc[1][1]); \
        FMA2(acc[1][2], q1, H.x, acc[1][2]); FMA2(acc[1][3], q1, H.y, acc[1][3]); \
        FMA2(acc[2][0], q2, L.x, acc[2][0]); FMA2(acc[2][1], q2, L.y, acc[2][1]); \
        FMA2(acc[2][2], q2, H.x, acc[2][2]); FMA2(acc[2][3], q2, H.y, acc[2][3]); \
        FMA2(acc[3][0], q3, L.x, acc[3][0]); FMA2(acc[3][1], q3, L.y, acc[3][1]); \
        FMA2(acc[3][2], q3, H.x, acc[3][2]); FMA2(acc[3][3], q3, H.y, acc[3][3]); \
        FMA2(acc[4][0], q4, L.x, acc[4][0]); FMA2(acc[4][1], q4, L.y, acc[4][1]); \
        FMA2(acc[4][2], q4, H.x, acc[4][2]); FMA2(acc[4][3], q4, H.y, acc[4][3]); \
        FMA2(acc[5][0], q5, L.x, acc[5][0]); FMA2(acc[5][1], q5, L.y, acc[5][1]); \
        FMA2(acc[5][2], q5, H.x, acc[5][2]); FMA2(acc[5][3], q5, H.y, acc[5][3]); \
        FMA2(acc[6][0], q6, L.x, acc[6][0]); FMA2(acc[6][1], q6, L.y, acc[6][1]); \
        FMA2(acc[6][2], q6, H.x, acc[6][2]); FMA2(acc[6][3], q6, H.y, acc[6][3]); \
        FMA2(acc[7][0], q7, L.x, acc[7][0]); FMA2(acc[7][1], q7, L.y, acc[7][1]); \
        FMA2(acc[7][2], q7, H.x, acc[7][2]); FMA2(acc[7][3], q7, H.y, acc[7][3]); \
    }

    #pragma unroll 1
    for (int tt = 0; tt < 24; tt++) {
        STEP(0,  0, bva)
        STEP(32, 2, bvb)
        STEP(64, 4, bvc)
        j += 96;
        s += 6;
    }
#undef STEP

    // reduce + write 8 rows
    #pragma unroll
    for (int r = 0; r < 8; r++) {
        float f0, f1, f2, f3, f4, f5, f6, f7;
        unsigned u0, u1;
        UNPK2(u0, u1, acc[r][0]); f0 = __uint_as_float(u0); f1 = __uint_as_float(u1);
        UNPK2(u0, u1, acc[r][1]); f2 = __uint_as_float(u0); f3 = __uint_as_float(u1);
        UNPK2(u0, u1, acc[r][2]); f4 = __uint_as_float(u0); f5 = __uint_as_float(u1);
        UNPK2(u0, u1, acc[r][3]); f6 = __uint_as_float(u0); f7 = __uint_as_float(u1);
        #pragma unroll
        for (int off = 16; off; off >>= 1) {
            f0 += __shfl_xor_sync(0xffffffffu, f0, off);
            f1 += __shfl_xor_sync(0xffffffffu, f1, off);
            f2 += __shfl_xor_sync(0xffffffffu, f2, off);
            f3 += __shfl_xor_sync(0xffffffffu, f3, off);
            f4 += __shfl_xor_sync(0xffffffffu, f4, off);
            f5 += __shfl_xor_sync(0xffffffffu, f5, off);
            f6 += __shfl_xor_sync(0xffffffffu, f6, off);
            f7 += __shfl_xor_sync(0xffffffffu, f7, off);
        }
        float rr = f0;
        if (lane == 1) rr = f1;
        if (lane == 2) rr = f2;
        if (lane == 3) rr = f3;
        if (lane == 4) rr = f4;
        if (lane == 5) rr = f5;
        if (lane == 6) rr = f6;
        if (lane == 7) rr = f7;
        if (lane < 8)
            out[((size_t)(b * 64) + hd * 8 + lane) * HW + i0 + r] = rr / rsum[r];
    }
}

// ---------------- launch ----------------
extern "C" void kernel_launch(void* const* d_in, const int* in_sizes, int n_in,
                              void* d_out, int out_size) {
    const float* f    = (const float*)d_in[0];
    const float* wqkv = (const float*)d_in[1];
    const float* wq   = (const float*)d_in[2];
    const float* bq   = (const float*)d_in[3];
    const float* wk   = (const float*)d_in[4];
    const float* bk   = (const float*)d_in[5];
    const float* ph   = (const float*)d_in[6];
    const float* pw   = (const float*)d_in[7];
    float* out = (float*)d_out;

    qkv_kernel<<<1152, 256>>>(f, wqkv);
    conv_kernel<<<512, 288>>>(wq, bq, wk, bk);
    attn_kernel<<<1152, 128>>>(ph, pw, out);
}